// round 12
// baseline (speedup 1.0000x reference)
#include <cuda_runtime.h>
#include <cuda_bf16.h>
#include <cstdint>
#include <cstddef>

#define NR 8192
#define DI 1024
#define DO 4096
#define C  32
#define KSEL 10
#define GAMMA_F 0.01618f
#define MARGIN 0.008f
#define FB_SLACK 0.03f
#define PFD 4                     // seq prefetch depth (rows)
#define NEGINF (-3.4e38f)

typedef unsigned long long ull;

// ---------------- static device scratch (no allocations allowed) ------------
__device__ __nv_bfloat16 g_xb[(size_t)NR * DI];   // 16 MB bf16 X
__device__ __nv_bfloat16 g_wb[(size_t)DO * DI];   //  8 MB bf16 W
__device__ float g_h[(size_t)NR * DO];            // 128 MB fp32 h (approx)
__device__ ull   g_cp[(size_t)(NR + PFD) * C];    // packed (h bits << 32) | idx
__device__ int   g_ci[NR * C];                    // candidate column indices
__device__ float g_cT[NR + PFD];                  // exact 33rd-largest approx h

// ---------------- asm helpers ----------------------------------------------
__device__ __forceinline__ uint32_t s2u(const void* p) {
    uint32_t a;
    asm("{ .reg .u64 t; cvta.to.shared.u64 t, %1; cvt.u32.u64 %0, t; }"
        : "=r"(a) : "l"(p));
    return a;
}
__device__ __forceinline__ void cpa16(uint32_t s, const void* g) {
    asm volatile("cp.async.cg.shared.global [%0], [%1], 16;" :: "r"(s), "l"(g));
}
#define CPA_COMMIT() asm volatile("cp.async.commit_group;" ::: "memory")
#define CPA_WAIT1()  asm volatile("cp.async.wait_group 1;" ::: "memory")

__device__ __forceinline__ void ldsm4(uint32_t* r, uint32_t addr) {
    asm volatile("ldmatrix.sync.aligned.m8n8.x4.shared.b16 {%0,%1,%2,%3},[%4];"
                 : "=r"(r[0]), "=r"(r[1]), "=r"(r[2]), "=r"(r[3]) : "r"(addr));
}
__device__ __forceinline__ void mma16816(float* c, const uint32_t* a, const uint32_t* b) {
    asm volatile("mma.sync.aligned.m16n8k16.row.col.f32.bf16.bf16.f32 "
                 "{%0,%1,%2,%3},{%4,%5,%6,%7},{%8,%9},{%0,%1,%2,%3};"
                 : "+f"(c[0]), "+f"(c[1]), "+f"(c[2]), "+f"(c[3])
                 : "r"(a[0]), "r"(a[1]), "r"(a[2]), "r"(a[3]), "r"(b[0]), "r"(b[1]));
}

// ---------------- Phase 0: zero output -------------------------------------
__global__ void zero_kernel(float4* __restrict__ p, int n4) {
    int i = blockIdx.x * blockDim.x + threadIdx.x;
    if (i < n4) p[i] = make_float4(0.f, 0.f, 0.f, 0.f);
}

// ---------------- Phase 0b: fp32 -> bf16 conversion ------------------------
__global__ void cvt_kernel(const float* __restrict__ X, const float* __restrict__ W) {
    const size_t NX4 = (size_t)NR * DI / 4;
    const size_t NW4 = (size_t)DO * DI / 4;
    size_t i = (size_t)blockIdx.x * blockDim.x + threadIdx.x;
    if (i >= NX4 + NW4) return;
    float4 v;
    uint2* dst;
    if (i < NX4) { v = ((const float4*)X)[i]; dst = (uint2*)g_xb + i; }
    else         { v = ((const float4*)W)[i - NX4]; dst = (uint2*)g_wb + (i - NX4); }
    uint32_t lo = (uint32_t)__bfloat16_as_ushort(__float2bfloat16_rn(v.x)) |
                  ((uint32_t)__bfloat16_as_ushort(__float2bfloat16_rn(v.y)) << 16);
    uint32_t hi = (uint32_t)__bfloat16_as_ushort(__float2bfloat16_rn(v.z)) |
                  ((uint32_t)__bfloat16_as_ushort(__float2bfloat16_rn(v.w)) << 16);
    *dst = make_uint2(lo, hi);
}

// ---------------- Phase 1: bf16 HMMA GEMM + bias + leaky -> fp32 h ---------
#define GBK 32
#define ROWB 80
#define TILEB (128 * ROWB)
#define STAGEB (2 * TILEB)
#define GSTAGES 3
#define GSMEM (GSTAGES * STAGEB)   // 61440

__global__ void __launch_bounds__(256, 1)
gemm_hmma(const float* __restrict__ bias) {
    extern __shared__ char sm[];
    const uint32_t sb = s2u(sm);
    const int tid = threadIdx.x;
    const int wid = tid >> 5, lane = tid & 31;
    const int row0 = blockIdx.y * 128;
    const int col0 = blockIdx.x * 128;
    const int wm = wid & 1, wn = wid >> 1;

    auto load_stage = [&](int kt, int s) {
        const uint32_t sbase = sb + s * STAGEB;
#pragma unroll
        for (int i = 0; i < 4; ++i) {
            int item = tid + i * 256;
            int isB = item >> 9;
            int r = (item >> 2) & 127;
            int c = item & 3;
            uint32_t sa = sbase + isB * TILEB + r * ROWB + c * 16;
            const uint4* g = isB
                ? (const uint4*)g_wb + ((size_t)(col0 + r) * (DI / 8) + kt * 4 + c)
                : (const uint4*)g_xb + ((size_t)(row0 + r) * (DI / 8) + kt * 4 + c);
            cpa16(sa, g);
        }
        CPA_COMMIT();
    };

    float acc[4][4][4];
#pragma unroll
    for (int i = 0; i < 4; ++i)
#pragma unroll
        for (int j = 0; j < 4; ++j)
#pragma unroll
            for (int q = 0; q < 4; ++q) acc[i][j][q] = 0.f;

    const int NT = DI / GBK;
    load_stage(0, 0);
    load_stage(1, 1);
    CPA_WAIT1();
    __syncthreads();

#pragma unroll 1
    for (int kt = 0; kt < NT; ++kt) {
        const uint32_t Ab = sb + (kt % 3) * STAGEB;
        const uint32_t Bb = Ab + TILEB;

        uint32_t a[4][2][4], b[2][2][4];
        const int arow_l = lane & 15;
        const int asel   = (lane >> 4) & 1;
        const int g      = lane >> 3;
#pragma unroll
        for (int im = 0; im < 4; ++im)
#pragma unroll
            for (int ks = 0; ks < 2; ++ks) {
                int arow = wm * 64 + im * 16 + arow_l;
                int ach  = ks * 2 + asel;
                ldsm4(a[im][ks], Ab + arow * ROWB + ach * 16);
            }
#pragma unroll
        for (int p = 0; p < 2; ++p)
#pragma unroll
            for (int ks = 0; ks < 2; ++ks) {
                int blk = p * 2 + (g >> 1);
                int ch  = ks * 2 + (g & 1);
                int nrow = wn * 32 + blk * 8 + (lane & 7);
                ldsm4(b[p][ks], Bb + nrow * ROWB + ch * 16);
            }
#pragma unroll
        for (int im = 0; im < 4; ++im)
#pragma unroll
            for (int p = 0; p < 2; ++p)
#pragma unroll
                for (int ks = 0; ks < 2; ++ks) {
                    mma16816(acc[im][p * 2 + 0], a[im][ks], &b[p][ks][0]);
                    mma16816(acc[im][p * 2 + 1], a[im][ks], &b[p][ks][2]);
                }

        if (kt + 2 < NT) load_stage(kt + 2, (kt + 2) % 3);
        else             CPA_COMMIT();
        CPA_WAIT1();
        __syncthreads();
    }

    // epilogue: bias + leaky -> fp32 g_h, direct float2 stores
#pragma unroll
    for (int im = 0; im < 4; ++im)
#pragma unroll
        for (int in = 0; in < 4; ++in) {
            int rl = wm * 64 + im * 16 + (lane >> 2);
            int cl = wn * 32 + in * 8 + (lane & 3) * 2;
            float b0v = bias[col0 + cl], b1v = bias[col0 + cl + 1];
#pragma unroll
            for (int half = 0; half < 2; ++half) {
                float f0 = acc[im][in][half * 2 + 0] + b0v;
                float f1 = acc[im][in][half * 2 + 1] + b1v;
                f0 = f0 > 0.f ? f0 : 0.01f * f0;
                f1 = f1 > 0.f ? f1 : 0.01f * f1;
                float2* dst = (float2*)(g_h + (size_t)(row0 + rl + half * 8) * DO + col0 + cl);
                *dst = make_float2(f0, f1);
            }
        }
}

// ---------------- Phase 2: per-row top-32 candidates (exact fp32 radix) ----
__global__ void __launch_bounds__(256)
cand_kernel() {
    const int row = blockIdx.x;
    const int tid = threadIdx.x;
    __shared__ unsigned skey[DO];    // 16 KB
    __shared__ unsigned hist[256];
    __shared__ unsigned s_pref;
    __shared__ int s_need, s_cnt;

    const float* h = g_h + (size_t)row * DO;
    for (int i = tid; i < DO; i += 256) {
        unsigned u = __float_as_uint(h[i]);
        u ^= (u >> 31) ? 0xFFFFFFFFu : 0x80000000u;   // monotone key
        skey[i] = u;
    }
    if (tid == 0) { s_pref = 0; s_need = C + 1; s_cnt = 0; }
    __syncthreads();

    for (int pass = 0; pass < 4; ++pass) {
        const int shift = 24 - 8 * pass;
        for (int i = tid; i < 256; i += 256) hist[i] = 0;
        __syncthreads();
        unsigned pref = s_pref;
        unsigned hm = (pass == 0) ? 0u : (0xFFFFFFFFu << (shift + 8));
        for (int i = tid; i < DO; i += 256) {
            unsigned k = skey[i];
            if (((k ^ pref) & hm) == 0) atomicAdd(&hist[(k >> shift) & 255], 1u);
        }
        __syncthreads();
        if (tid == 0) {
            int need = s_need, acc = 0, b = 255;
            for (; b >= 0; --b) { acc += (int)hist[b]; if (acc >= need) break; }
            if (b < 0) b = 0;                       // defensive (invariant holds)
            s_need = need - (acc - (int)hist[b]);
            s_pref = pref | ((unsigned)b << shift);
        }
        __syncthreads();
    }
    const unsigned K33 = s_pref;

    for (int i = tid; i < DO; i += 256) {
        if (skey[i] > K33) {
            int p = atomicAdd(&s_cnt, 1);
            if (p < C) g_ci[row * C + p] = i;       // defensive bound
        }
    }
    __syncthreads();
    for (int i = tid; i < DO; i += 256) {
        if (skey[i] == K33) {
            int p = atomicAdd(&s_cnt, 1);
            if (p < C) g_ci[row * C + p] = i;
        }
    }
    __syncthreads();
    if (tid < 32) {   // bitonic sort candidate indices ascending
        int v = g_ci[row * C + tid];
#pragma unroll
        for (int k2 = 2; k2 <= 32; k2 <<= 1)
#pragma unroll
            for (int j = k2 >> 1; j > 0; j >>= 1) {
                int pv = __shfl_xor_sync(0xFFFFFFFFu, v, j);
                bool up = ((tid & k2) == 0);
                bool takemin = (((tid & j) == 0) == up);
                int mn = v < pv ? v : pv, mx = v < pv ? pv : v;
                v = takemin ? mn : mx;
            }
        g_ci[row * C + tid] = v;
        if (tid == 0) {
            unsigned k = K33;
            g_cT[row] = __uint_as_float((k & 0x80000000u) ? (k ^ 0x80000000u) : ~k);
        }
    }
}

// ---------------- Phase 3: compensated-fp32 exact refinement ---------------
__global__ void __launch_bounds__(1024)
refine_kernel(const float* __restrict__ X, const float* __restrict__ W,
              const float* __restrict__ bias) {
    const int row = blockIdx.x, tid = threadIdx.x;
    const int w = tid >> 5, lane = tid & 31;
    __shared__ float sx[DI];
    sx[tid] = X[(size_t)row * DI + tid];
    __syncthreads();

    const int ci = g_ci[row * C + w];
    const float* wr = W + (size_t)ci * DI;
    float hi = 0.f, lo = 0.f;
#pragma unroll 8
    for (int i = 0; i < DI / 32; ++i) {
        int kk = i * 32 + lane;
        float a = sx[kk], b = wr[kk];
        float p  = __fmul_rn(a, b);
        float pe = __fmaf_rn(a, b, -p);
        float t  = __fadd_rn(hi, p);
        float bp = __fsub_rn(t, hi);
        float e  = __fadd_rn(__fsub_rn(hi, __fsub_rn(t, bp)), __fsub_rn(p, bp));
        hi = t;
        lo = __fadd_rn(lo, __fadd_rn(e, pe));
    }
    double d = (double)hi + (double)lo;
#pragma unroll
    for (int off = 16; off; off >>= 1) d += __shfl_xor_sync(0xFFFFFFFFu, d, off);
    if (lane == 0) {
        float hv = (float)d;                 // correctly-rounded exact dot
        hv = __fadd_rn(hv, bias[ci]);
        hv = (hv > 0.f) ? hv : __fmul_rn(0.01f, hv);
        g_cp[(size_t)row * C + w] =
            ((ull)(unsigned)__float_as_uint(hv) << 32) | (unsigned)ci;
    }
}

// ---------------- Phase 4: sequential recurrence (one warp) ----------------
#define FB_CAP 512

__device__ __noinline__ void fallback_row(const float* __restrict__ X,
                                          const float* __restrict__ W,
                                          const float* __restrict__ bias,
                                          float* __restrict__ out, int t,
                                          int* s_lr, float* s_s, float* s_x,
                                          int* s_cand, float* s_cs, int* s_nc,
                                          const float* s_chain, int lane) {
    // 1) approx s from fp32 h for all columns
    const float* hrow = g_h + (size_t)t * DO;
    for (int col = lane; col < DO; col += 32) {
        int age = t - s_lr[col] - 1; if (age > 63) age = 63;
        s_s[col] = hrow[col] * s_chain[age];
    }
    if (lane == 0) *s_nc = KSEL;      // slots 0..9 pre-seeded below
    __syncwarp();

    // 2) 10 arg-max rounds over smem (no register array -> no spills).
    //    Winning slot is tombstoned and pre-seeded into s_cand.
    float t10b = NEGINF;
    for (int r = 0; r < KSEL; ++r) {
        float bv = NEGINF; int bi = lane;
        for (int i = lane; i < DO; i += 32) {
            float v = s_s[i];
            if (v > bv) { bv = v; bi = i; }
        }
        float lbv = bv; int lbi = bi;
#pragma unroll
        for (int off = 16; off; off >>= 1) {
            float ov = __shfl_xor_sync(0xFFFFFFFFu, bv, off);
            int   oi = __shfl_xor_sync(0xFFFFFFFFu, bi, off);
            if (ov > bv || (ov == bv && oi < bi)) { bv = ov; bi = oi; }
        }
        t10b = bv;
        if (lbi == bi && lbv == bv) {      // owner lane (indices distinct mod 32)
            s_s[bi] = NEGINF;
            s_cand[r] = bi;
        }
        __syncwarp();
    }

    // 3) sound candidate set (tombstoned slots already in s_cand[0..9])
    const float thr = t10b - FB_SLACK;
    for (int col = lane; col < DO; col += 32) {
        if (s_s[col] >= thr) {
            int p = atomicAdd(s_nc, 1);
            if (p < FB_CAP) s_cand[p] = col;
        }
    }
    __syncwarp();
    int nc = *s_nc; if (nc > FB_CAP) nc = FB_CAP;   // overflow: practically never

    // X row to shared
    for (int i = lane; i < DI; i += 32) s_x[i] = X[(size_t)t * DI + i];
    __syncwarp();

    // 4) cooperative exact fp64 refine per candidate column (coalesced)
    for (int c = 0; c < nc; ++c) {
        const int col = s_cand[c];
        const float* wr = W + (size_t)col * DI;
        double d0 = 0, d1 = 0, d2 = 0, d3 = 0;
#pragma unroll 4
        for (int q = 0; q < DI / 32; q += 4) {
            d0 = fma((double)s_x[lane + 32 * (q + 0)], (double)wr[lane + 32 * (q + 0)], d0);
            d1 = fma((double)s_x[lane + 32 * (q + 1)], (double)wr[lane + 32 * (q + 1)], d1);
            d2 = fma((double)s_x[lane + 32 * (q + 2)], (double)wr[lane + 32 * (q + 2)], d2);
            d3 = fma((double)s_x[lane + 32 * (q + 3)], (double)wr[lane + 32 * (q + 3)], d3);
        }
        double d = (d0 + d1) + (d2 + d3);
#pragma unroll
        for (int off = 16; off; off >>= 1) d += __shfl_xor_sync(0xFFFFFFFFu, d, off);
        if (lane == 0) {
            float hv = (float)d;
            hv = __fadd_rn(hv, bias[col]);
            hv = hv > 0.f ? hv : __fmul_rn(0.01f, hv);
            int age = t - s_lr[col] - 1; if (age > 63) age = 63;
            s_cs[c] = __fmul_rn(hv, s_chain[age]);
        }
    }
    __syncwarp();

    // 5) exact top-10 (value desc, column asc tiebreak)
    for (int r = 0; r < KSEL; ++r) {
        float bv = NEGINF; int bcol = 1 << 30, bslot = 0;
        for (int c = lane; c < nc; c += 32) {
            float v = s_cs[c]; int col = s_cand[c];
            if (v > bv || (v == bv && col < bcol)) { bv = v; bcol = col; bslot = c; }
        }
#pragma unroll
        for (int off = 16; off; off >>= 1) {
            float ov = __shfl_xor_sync(0xFFFFFFFFu, bv, off);
            int   oc = __shfl_xor_sync(0xFFFFFFFFu, bcol, off);
            int   os = __shfl_xor_sync(0xFFFFFFFFu, bslot, off);
            if (ov > bv || (ov == bv && oc < bcol)) { bv = ov; bcol = oc; bslot = os; }
        }
        if (!(bv > 0.f)) break;
        if (lane == 0) {
            out[(size_t)t * DO + bcol] = 1.0f;
            s_lr[bcol] = t;
            s_cs[bslot] = NEGINF;
        }
        __syncwarp();
    }
    __syncwarp();
}

__global__ void __launch_bounds__(32)
seq_kernel(const float* __restrict__ X, const float* __restrict__ W,
           const float* __restrict__ bias, float* __restrict__ out) {
    __shared__ int   s_lr[DO];
    __shared__ float s_s[DO];
    __shared__ float s_x[DI];
    __shared__ int   s_cand[FB_CAP];
    __shared__ float s_cs[FB_CAP];
    __shared__ float s_chain[64];
    __shared__ __align__(16) unsigned s_keys[32];
    __shared__ float s_v10;
    __shared__ int   s_nc;
    const int lane = threadIdx.x;

    for (int i = lane; i < DO; i += 32) s_lr[i] = -1000000;
    if (lane == 0) {
        float c = 0.f;
        s_chain[0] = 0.f;
        for (int i = 1; i < 64; ++i) {
            c = fminf(__fadd_rn(c, GAMMA_F), 1.0f);
            s_chain[i] = c;
        }
    }
    __syncwarp();

    // depth-PFD register prefetch ring: DRAM latency covered by ~PFD iterations
    ull   pbuf[PFD];
    float tbuf[PFD];
#pragma unroll
    for (int i = 0; i < PFD; ++i) {
        pbuf[i] = g_cp[(size_t)i * C + lane];
        tbuf[i] = g_cT[i];
    }

#pragma unroll 4
    for (int t = 0; t < NR; ++t) {
        const int slot = t & (PFD - 1);
        const ull   pk = pbuf[slot];
        const float T  = tbuf[slot];
        // prefetch row t+PFD into the freed slot (in-bounds: arrays padded)
        pbuf[slot] = g_cp[(size_t)(t + PFD) * C + lane];
        tbuf[slot] = g_cT[t + PFD];

        const int   myidx = (int)(pk & 0xFFFFFFFFu);
        const float myh   = __uint_as_float((unsigned)(pk >> 32));

        int lr = s_lr[myidx];
        int age = t - lr - 1; if (age > 63) age = 63;
        float s = __fmul_rn(myh, s_chain[age]);
        if (s == 0.0f) s = 0.0f;          // canonicalize -0.0 -> +0.0

        // monotone key; total order (key desc, lane asc) => rank is a bijection
        unsigned u = __float_as_uint(s);
        u ^= (u >> 31) ? 0xFFFFFFFFu : 0x80000000u;
        s_keys[lane] = u;
        __syncwarp();

        int cnt = 0;
#pragma unroll
        for (int j = 0; j < 8; ++j) {
            uint4 k = *(const uint4*)&s_keys[4 * j];
            cnt += (k.x > u) || (k.x == u && (4 * j + 0) < lane);
            cnt += (k.y > u) || (k.y == u && (4 * j + 1) < lane);
            cnt += (k.z > u) || (k.z == u && (4 * j + 2) < lane);
            cnt += (k.w > u) || (k.w == u && (4 * j + 3) < lane);
        }
        if (cnt == 9) s_v10 = s;          // exactly one lane (bijection)
        __syncwarp();
        const float v10 = s_v10;

        if (v10 > T + MARGIN) {           // certificate: candidate top-10 == global
            if (cnt < KSEL && s > 0.f) {
                out[(size_t)t * DO + myidx] = 1.0f;
                s_lr[myidx] = t;
            }
        } else {
            fallback_row(X, W, bias, out, t, s_lr, s_s, s_x,
                         s_cand, s_cs, &s_nc, s_chain, lane);
        }
        __syncwarp();
    }
}

// ---------------- launch ----------------------------------------------------
extern "C" void kernel_launch(void* const* d_in, const int* in_sizes, int n_in,
                              void* d_out, int out_size) {
    const float* X    = (const float*)d_in[0];
    const float* W    = (const float*)d_in[1];
    const float* bias = (const float*)d_in[2];
    float* out = (float*)d_out;

    const int n4 = NR * DO / 4;
    zero_kernel<<<(n4 + 255) / 256, 256>>>((float4*)out, n4);

    const size_t ncv = ((size_t)NR * DI + (size_t)DO * DI) / 4;
    cvt_kernel<<<(int)((ncv + 255) / 256), 256>>>(X, W);

    cudaFuncSetAttribute(gemm_hmma, cudaFuncAttributeMaxDynamicSharedMemorySize, GSMEM);
    dim3 gg(DO / 128, NR / 128);
    gemm_hmma<<<gg, 256, GSMEM>>>(bias);

    cand_kernel<<<NR, 256>>>();
    refine_kernel<<<NR, 1024>>>(X, W, bias);
    seq_kernel<<<1, 32>>>(X, W, bias, out);
}

// round 13
// speedup vs baseline: 1.0257x; 1.0257x over previous
#include <cuda_runtime.h>
#include <cuda_bf16.h>
#include <cstdint>
#include <cstddef>

#define NR 8192
#define DI 1024
#define DO 4096
#define C  32
#define KSEL 10
#define GAMMA_F 0.01618f
#define MARGIN 0.008f
#define FB_SLACK 0.03f
#define NEGINF (-3.4e38f)

typedef unsigned long long ull;

// ---------------- static device scratch (no allocations allowed) ------------
__device__ __nv_bfloat16 g_xb[(size_t)NR * DI];   // 16 MB bf16 X
__device__ __nv_bfloat16 g_wb[(size_t)DO * DI];   //  8 MB bf16 W
__device__ float g_h[(size_t)NR * DO];            // 128 MB fp32 h (approx)
__device__ ull   g_cp[(size_t)NR * C];            // packed (h bits << 32) | idx
__device__ int   g_ci[NR * C];                    // candidate column indices
__device__ float g_cT[NR];                        // exact 33rd-largest approx h

// ---------------- asm helpers ----------------------------------------------
__device__ __forceinline__ uint32_t s2u(const void* p) {
    uint32_t a;
    asm("{ .reg .u64 t; cvta.to.shared.u64 t, %1; cvt.u32.u64 %0, t; }"
        : "=r"(a) : "l"(p));
    return a;
}
__device__ __forceinline__ void cpa16(uint32_t s, const void* g) {
    asm volatile("cp.async.cg.shared.global [%0], [%1], 16;" :: "r"(s), "l"(g));
}
#define CPA_COMMIT() asm volatile("cp.async.commit_group;" ::: "memory")
#define CPA_WAIT1()  asm volatile("cp.async.wait_group 1;" ::: "memory")
#define CPA_WAIT0()  asm volatile("cp.async.wait_group 0;" ::: "memory")

__device__ __forceinline__ void ldsm4(uint32_t* r, uint32_t addr) {
    asm volatile("ldmatrix.sync.aligned.m8n8.x4.shared.b16 {%0,%1,%2,%3},[%4];"
                 : "=r"(r[0]), "=r"(r[1]), "=r"(r[2]), "=r"(r[3]) : "r"(addr));
}
__device__ __forceinline__ void mma16816(float* c, const uint32_t* a, const uint32_t* b) {
    asm volatile("mma.sync.aligned.m16n8k16.row.col.f32.bf16.bf16.f32 "
                 "{%0,%1,%2,%3},{%4,%5,%6,%7},{%8,%9},{%0,%1,%2,%3};"
                 : "+f"(c[0]), "+f"(c[1]), "+f"(c[2]), "+f"(c[3])
                 : "r"(a[0]), "r"(a[1]), "r"(a[2]), "r"(a[3]), "r"(b[0]), "r"(b[1]));
}

// ---------------- Phase 0: zero output -------------------------------------
__global__ void zero_kernel(float4* __restrict__ p, int n4) {
    int i = blockIdx.x * blockDim.x + threadIdx.x;
    if (i < n4) p[i] = make_float4(0.f, 0.f, 0.f, 0.f);
}

// ---------------- Phase 0b: fp32 -> bf16 conversion ------------------------
__global__ void cvt_kernel(const float* __restrict__ X, const float* __restrict__ W) {
    const size_t NX4 = (size_t)NR * DI / 4;
    const size_t NW4 = (size_t)DO * DI / 4;
    size_t i = (size_t)blockIdx.x * blockDim.x + threadIdx.x;
    if (i >= NX4 + NW4) return;
    float4 v;
    uint2* dst;
    if (i < NX4) { v = ((const float4*)X)[i]; dst = (uint2*)g_xb + i; }
    else         { v = ((const float4*)W)[i - NX4]; dst = (uint2*)g_wb + (i - NX4); }
    uint32_t lo = (uint32_t)__bfloat16_as_ushort(__float2bfloat16_rn(v.x)) |
                  ((uint32_t)__bfloat16_as_ushort(__float2bfloat16_rn(v.y)) << 16);
    uint32_t hi = (uint32_t)__bfloat16_as_ushort(__float2bfloat16_rn(v.z)) |
                  ((uint32_t)__bfloat16_as_ushort(__float2bfloat16_rn(v.w)) << 16);
    *dst = make_uint2(lo, hi);
}

// ---------------- Phase 1: bf16 HMMA GEMM + bias + leaky -> fp32 h ---------
#define GBK 32
#define ROWB 80
#define TILEB (128 * ROWB)
#define STAGEB (2 * TILEB)
#define GSTAGES 3
#define GSMEM (GSTAGES * STAGEB)   // 61440

__global__ void __launch_bounds__(256, 1)
gemm_hmma(const float* __restrict__ bias) {
    extern __shared__ char sm[];
    const uint32_t sb = s2u(sm);
    const int tid = threadIdx.x;
    const int wid = tid >> 5, lane = tid & 31;
    const int row0 = blockIdx.y * 128;
    const int col0 = blockIdx.x * 128;
    const int wm = wid & 1, wn = wid >> 1;

    auto load_stage = [&](int kt, int s) {
        const uint32_t sbase = sb + s * STAGEB;
#pragma unroll
        for (int i = 0; i < 4; ++i) {
            int item = tid + i * 256;
            int isB = item >> 9;
            int r = (item >> 2) & 127;
            int c = item & 3;
            uint32_t sa = sbase + isB * TILEB + r * ROWB + c * 16;
            const uint4* g = isB
                ? (const uint4*)g_wb + ((size_t)(col0 + r) * (DI / 8) + kt * 4 + c)
                : (const uint4*)g_xb + ((size_t)(row0 + r) * (DI / 8) + kt * 4 + c);
            cpa16(sa, g);
        }
        CPA_COMMIT();
    };

    float acc[4][4][4];
#pragma unroll
    for (int i = 0; i < 4; ++i)
#pragma unroll
        for (int j = 0; j < 4; ++j)
#pragma unroll
            for (int q = 0; q < 4; ++q) acc[i][j][q] = 0.f;

    const int NT = DI / GBK;
    load_stage(0, 0);
    load_stage(1, 1);
    CPA_WAIT1();
    __syncthreads();

#pragma unroll 1
    for (int kt = 0; kt < NT; ++kt) {
        const uint32_t Ab = sb + (kt % 3) * STAGEB;
        const uint32_t Bb = Ab + TILEB;

        uint32_t a[4][2][4], b[2][2][4];
        const int arow_l = lane & 15;
        const int asel   = (lane >> 4) & 1;
        const int g      = lane >> 3;
#pragma unroll
        for (int im = 0; im < 4; ++im)
#pragma unroll
            for (int ks = 0; ks < 2; ++ks) {
                int arow = wm * 64 + im * 16 + arow_l;
                int ach  = ks * 2 + asel;
                ldsm4(a[im][ks], Ab + arow * ROWB + ach * 16);
            }
#pragma unroll
        for (int p = 0; p < 2; ++p)
#pragma unroll
            for (int ks = 0; ks < 2; ++ks) {
                int blk = p * 2 + (g >> 1);
                int ch  = ks * 2 + (g & 1);
                int nrow = wn * 32 + blk * 8 + (lane & 7);
                ldsm4(b[p][ks], Bb + nrow * ROWB + ch * 16);
            }
#pragma unroll
        for (int im = 0; im < 4; ++im)
#pragma unroll
            for (int p = 0; p < 2; ++p)
#pragma unroll
                for (int ks = 0; ks < 2; ++ks) {
                    mma16816(acc[im][p * 2 + 0], a[im][ks], &b[p][ks][0]);
                    mma16816(acc[im][p * 2 + 1], a[im][ks], &b[p][ks][2]);
                }

        if (kt + 2 < NT) load_stage(kt + 2, (kt + 2) % 3);
        else             CPA_COMMIT();
        CPA_WAIT1();
        __syncthreads();
    }

    // epilogue: bias + leaky -> fp32 g_h, direct float2 stores
#pragma unroll
    for (int im = 0; im < 4; ++im)
#pragma unroll
        for (int in = 0; in < 4; ++in) {
            int rl = wm * 64 + im * 16 + (lane >> 2);
            int cl = wn * 32 + in * 8 + (lane & 3) * 2;
            float b0v = bias[col0 + cl], b1v = bias[col0 + cl + 1];
#pragma unroll
            for (int half = 0; half < 2; ++half) {
                float f0 = acc[im][in][half * 2 + 0] + b0v;
                float f1 = acc[im][in][half * 2 + 1] + b1v;
                f0 = f0 > 0.f ? f0 : 0.01f * f0;
                f1 = f1 > 0.f ? f1 : 0.01f * f1;
                float2* dst = (float2*)(g_h + (size_t)(row0 + rl + half * 8) * DO + col0 + cl);
                *dst = make_float2(f0, f1);
            }
        }
}

// ---------------- Phase 2: per-row top-32 candidates (exact fp32 radix) ----
__global__ void __launch_bounds__(256)
cand_kernel() {
    const int row = blockIdx.x;
    const int tid = threadIdx.x;
    __shared__ unsigned skey[DO];    // 16 KB
    __shared__ unsigned hist[256];
    __shared__ unsigned s_pref;
    __shared__ int s_need, s_cnt;

    const float* h = g_h + (size_t)row * DO;
    for (int i = tid; i < DO; i += 256) {
        unsigned u = __float_as_uint(h[i]);
        u ^= (u >> 31) ? 0xFFFFFFFFu : 0x80000000u;   // monotone key
        skey[i] = u;
    }
    if (tid == 0) { s_pref = 0; s_need = C + 1; s_cnt = 0; }
    __syncthreads();

    for (int pass = 0; pass < 4; ++pass) {
        const int shift = 24 - 8 * pass;
        for (int i = tid; i < 256; i += 256) hist[i] = 0;
        __syncthreads();
        unsigned pref = s_pref;
        unsigned hm = (pass == 0) ? 0u : (0xFFFFFFFFu << (shift + 8));
        for (int i = tid; i < DO; i += 256) {
            unsigned k = skey[i];
            if (((k ^ pref) & hm) == 0) atomicAdd(&hist[(k >> shift) & 255], 1u);
        }
        __syncthreads();
        if (tid == 0) {
            int need = s_need, acc = 0, b = 255;
            for (; b >= 0; --b) { acc += (int)hist[b]; if (acc >= need) break; }
            if (b < 0) b = 0;                       // defensive (invariant holds)
            s_need = need - (acc - (int)hist[b]);
            s_pref = pref | ((unsigned)b << shift);
        }
        __syncthreads();
    }
    const unsigned K33 = s_pref;

    for (int i = tid; i < DO; i += 256) {
        if (skey[i] > K33) {
            int p = atomicAdd(&s_cnt, 1);
            if (p < C) g_ci[row * C + p] = i;       // defensive bound
        }
    }
    __syncthreads();
    for (int i = tid; i < DO; i += 256) {
        if (skey[i] == K33) {
            int p = atomicAdd(&s_cnt, 1);
            if (p < C) g_ci[row * C + p] = i;
        }
    }
    __syncthreads();
    if (tid < 32) {   // bitonic sort candidate indices ascending
        int v = g_ci[row * C + tid];
#pragma unroll
        for (int k2 = 2; k2 <= 32; k2 <<= 1)
#pragma unroll
            for (int j = k2 >> 1; j > 0; j >>= 1) {
                int pv = __shfl_xor_sync(0xFFFFFFFFu, v, j);
                bool up = ((tid & k2) == 0);
                bool takemin = (((tid & j) == 0) == up);
                int mn = v < pv ? v : pv, mx = v < pv ? pv : v;
                v = takemin ? mn : mx;
            }
        g_ci[row * C + tid] = v;
        if (tid == 0) {
            unsigned k = K33;
            g_cT[row] = __uint_as_float((k & 0x80000000u) ? (k ^ 0x80000000u) : ~k);
        }
    }
}

// ---------------- Phase 3: compensated-fp32 exact refinement ---------------
__global__ void __launch_bounds__(1024)
refine_kernel(const float* __restrict__ X, const float* __restrict__ W,
              const float* __restrict__ bias) {
    const int row = blockIdx.x, tid = threadIdx.x;
    const int w = tid >> 5, lane = tid & 31;
    __shared__ float sx[DI];
    sx[tid] = X[(size_t)row * DI + tid];
    __syncthreads();

    const int ci = g_ci[row * C + w];
    const float* wr = W + (size_t)ci * DI;
    float hi = 0.f, lo = 0.f;
#pragma unroll 8
    for (int i = 0; i < DI / 32; ++i) {
        int kk = i * 32 + lane;
        float a = sx[kk], b = wr[kk];
        float p  = __fmul_rn(a, b);
        float pe = __fmaf_rn(a, b, -p);
        float t  = __fadd_rn(hi, p);
        float bp = __fsub_rn(t, hi);
        float e  = __fadd_rn(__fsub_rn(hi, __fsub_rn(t, bp)), __fsub_rn(p, bp));
        hi = t;
        lo = __fadd_rn(lo, __fadd_rn(e, pe));
    }
    double d = (double)hi + (double)lo;
#pragma unroll
    for (int off = 16; off; off >>= 1) d += __shfl_xor_sync(0xFFFFFFFFu, d, off);
    if (lane == 0) {
        float hv = (float)d;                 // correctly-rounded exact dot
        hv = __fadd_rn(hv, bias[ci]);
        hv = (hv > 0.f) ? hv : __fmul_rn(0.01f, hv);
        g_cp[(size_t)row * C + w] =
            ((ull)(unsigned)__float_as_uint(hv) << 32) | (unsigned)ci;
    }
}

// ---------------- Phase 4: sequential recurrence (one warp, smem-staged) ---
#define FB_CAP 512
#define CHR 256                          // rows per staged chunk
#define NCH (NR / CHR)                   // 32
#define CH_BYTES (CHR * C * 8)           // 65536 per buffer
#define CT_BYTES (CHR * 4)               // 1024 per buffer

// dynamic smem layout (bytes)
#define SM_LR    0                       // int[4096]        16384
#define SM_SS    16384                   // float[4096]      16384
#define SM_SX    32768                   // float[1024]       4096
#define SM_CAND  36864                   // int[512]          2048
#define SM_CS    38912                   // float[512]        2048
#define SM_CHAIN 40960                   // float[64]          256
#define SM_KEYS  41216                   // unsigned[32]       128
#define SM_NC    41344                   // int                 16
#define SM_CBUF  41472                   // 2 x 65536       131072
#define SM_CT    172544                  // 2 x 1024          2048
#define SEQ_SMEM 174592

__device__ __noinline__ void fallback_row(const float* __restrict__ X,
                                          const float* __restrict__ W,
                                          const float* __restrict__ bias,
                                          float* __restrict__ out, int t,
                                          int* s_lr, float* s_s, float* s_x,
                                          int* s_cand, float* s_cs, int* s_nc,
                                          const float* s_chain, int lane) {
    // 1) approx s from fp32 h for all columns
    const float* hrow = g_h + (size_t)t * DO;
    for (int col = lane; col < DO; col += 32) {
        int age = t - s_lr[col] - 1; if (age > 63) age = 63;
        s_s[col] = hrow[col] * s_chain[age];
    }
    if (lane == 0) *s_nc = KSEL;      // slots 0..9 pre-seeded below
    __syncwarp();

    // 2) 10 arg-max rounds over smem; winner tombstoned + seeded into s_cand
    float t10b = NEGINF;
    for (int r = 0; r < KSEL; ++r) {
        float bv = NEGINF; int bi = lane;
        for (int i = lane; i < DO; i += 32) {
            float v = s_s[i];
            if (v > bv) { bv = v; bi = i; }
        }
        float lbv = bv; int lbi = bi;
#pragma unroll
        for (int off = 16; off; off >>= 1) {
            float ov = __shfl_xor_sync(0xFFFFFFFFu, bv, off);
            int   oi = __shfl_xor_sync(0xFFFFFFFFu, bi, off);
            if (ov > bv || (ov == bv && oi < bi)) { bv = ov; bi = oi; }
        }
        t10b = bv;
        if (lbi == bi && lbv == bv) {      // owner lane
            s_s[bi] = NEGINF;
            s_cand[r] = bi;
        }
        __syncwarp();
    }

    // 3) sound candidate set
    const float thr = t10b - FB_SLACK;
    for (int col = lane; col < DO; col += 32) {
        if (s_s[col] >= thr) {
            int p = atomicAdd(s_nc, 1);
            if (p < FB_CAP) s_cand[p] = col;
        }
    }
    __syncwarp();
    int nc = *s_nc; if (nc > FB_CAP) nc = FB_CAP;

    // X row to shared
    for (int i = lane; i < DI; i += 32) s_x[i] = X[(size_t)t * DI + i];
    __syncwarp();

    // 4) cooperative exact fp64 refine per candidate column (coalesced)
    for (int c = 0; c < nc; ++c) {
        const int col = s_cand[c];
        const float* wr = W + (size_t)col * DI;
        double d0 = 0, d1 = 0, d2 = 0, d3 = 0;
#pragma unroll 4
        for (int q = 0; q < DI / 32; q += 4) {
            d0 = fma((double)s_x[lane + 32 * (q + 0)], (double)wr[lane + 32 * (q + 0)], d0);
            d1 = fma((double)s_x[lane + 32 * (q + 1)], (double)wr[lane + 32 * (q + 1)], d1);
            d2 = fma((double)s_x[lane + 32 * (q + 2)], (double)wr[lane + 32 * (q + 2)], d2);
            d3 = fma((double)s_x[lane + 32 * (q + 3)], (double)wr[lane + 32 * (q + 3)], d3);
        }
        double d = (d0 + d1) + (d2 + d3);
#pragma unroll
        for (int off = 16; off; off >>= 1) d += __shfl_xor_sync(0xFFFFFFFFu, d, off);
        if (lane == 0) {
            float hv = (float)d;
            hv = __fadd_rn(hv, bias[col]);
            hv = hv > 0.f ? hv : __fmul_rn(0.01f, hv);
            int age = t - s_lr[col] - 1; if (age > 63) age = 63;
            s_cs[c] = __fmul_rn(hv, s_chain[age]);
        }
    }
    __syncwarp();

    // 5) exact top-10 (value desc, column asc tiebreak)
    for (int r = 0; r < KSEL; ++r) {
        float bv = NEGINF; int bcol = 1 << 30, bslot = 0;
        for (int c = lane; c < nc; c += 32) {
            float v = s_cs[c]; int col = s_cand[c];
            if (v > bv || (v == bv && col < bcol)) { bv = v; bcol = col; bslot = c; }
        }
#pragma unroll
        for (int off = 16; off; off >>= 1) {
            float ov = __shfl_xor_sync(0xFFFFFFFFu, bv, off);
            int   oc = __shfl_xor_sync(0xFFFFFFFFu, bcol, off);
            int   os = __shfl_xor_sync(0xFFFFFFFFu, bslot, off);
            if (ov > bv || (ov == bv && oc < bcol)) { bv = ov; bcol = oc; bslot = os; }
        }
        if (!(bv > 0.f)) break;
        if (lane == 0) {
            out[(size_t)t * DO + bcol] = 1.0f;
            s_lr[bcol] = t;
            s_cs[bslot] = NEGINF;
        }
        __syncwarp();
    }
    __syncwarp();
}

__global__ void __launch_bounds__(32)
seq_kernel(const float* __restrict__ X, const float* __restrict__ W,
           const float* __restrict__ bias, float* __restrict__ out) {
    extern __shared__ char dsm[];
    const uint32_t sb = s2u(dsm);
    int*      s_lr    = (int*)(dsm + SM_LR);
    float*    s_s     = (float*)(dsm + SM_SS);
    float*    s_x     = (float*)(dsm + SM_SX);
    int*      s_cand  = (int*)(dsm + SM_CAND);
    float*    s_cs    = (float*)(dsm + SM_CS);
    float*    s_chain = (float*)(dsm + SM_CHAIN);
    unsigned* s_keys  = (unsigned*)(dsm + SM_KEYS);
    int*      s_nc    = (int*)(dsm + SM_NC);
    const int lane = threadIdx.x;

    for (int i = lane; i < DO; i += 32) s_lr[i] = -1000000;
    if (lane == 0) {
        float c = 0.f;
        s_chain[0] = 0.f;
        for (int i = 1; i < 64; ++i) {
            c = fminf(__fadd_rn(c, GAMMA_F), 1.0f);
            s_chain[i] = c;
        }
    }
    __syncwarp();

    // chunk loader: stage 256 rows of packed candidates + thresholds to smem
    auto issue_chunk = [&](int ch) {
        const char* gsrc = (const char*)g_cp + (size_t)ch * CH_BYTES;
        uint32_t sdst = sb + SM_CBUF + (ch & 1) * CH_BYTES;
        for (int i = 0; i < CH_BYTES / 512; ++i)
            cpa16(sdst + lane * 16 + i * 512, gsrc + lane * 16 + i * 512);
        const char* gct = (const char*)g_cT + (size_t)ch * CT_BYTES;
        uint32_t sct = sb + SM_CT + (ch & 1) * CT_BYTES;
        if (lane < CT_BYTES / 32)            // 1024B: 32 lanes x2? -> lanes cover
            cpa16(sct + lane * 16, gct + lane * 16);
        if (lane < CT_BYTES / 32)
            cpa16(sct + 512 + lane * 16, gct + 512 + lane * 16);
        CPA_COMMIT();
    };

    issue_chunk(0);
    issue_chunk(1);
    CPA_WAIT1();
    __syncwarp();

    for (int ch = 0; ch < NCH; ++ch) {
        const char* cbuf = dsm + SM_CBUF + (ch & 1) * CH_BYTES;
        const char* ctb  = dsm + SM_CT   + (ch & 1) * CT_BYTES;

        for (int r = 0; r < CHR; ++r) {
            const int t = (ch << 8) + r;
            const ull pk  = *(const ull*)(cbuf + r * (C * 8) + lane * 8);
            const float T = *(const float*)(ctb + r * 4);
            const int   myidx = (int)(pk & 0xFFFFFFFFu);
            const float myh   = __uint_as_float((unsigned)(pk >> 32));

            int lr = s_lr[myidx];
            int age = t - lr - 1; if (age > 63) age = 63;
            float s = __fmul_rn(myh, s_chain[age]);
            if (s == 0.0f) s = 0.0f;          // canonicalize -0.0 -> +0.0

            unsigned u = __float_as_uint(s);
            u ^= (u >> 31) ? 0xFFFFFFFFu : 0x80000000u;
            s_keys[lane] = u;
            __syncwarp();

            int cnt = 0;
#pragma unroll
            for (int j = 0; j < 8; ++j) {
                uint4 k = *(const uint4*)&s_keys[4 * j];
                cnt += (k.x > u) || (k.x == u && (4 * j + 0) < lane);
                cnt += (k.y > u) || (k.y == u && (4 * j + 1) < lane);
                cnt += (k.z > u) || (k.z == u && (4 * j + 2) < lane);
                cnt += (k.w > u) || (k.w == u && (4 * j + 3) < lane);
            }
            unsigned m9 = __ballot_sync(0xFFFFFFFFu, cnt == 9);
            float v10 = __shfl_sync(0xFFFFFFFFu, s, m9 ? (__ffs(m9) - 1) : 0);
            bool ok = m9 && (v10 > T + MARGIN);

            if (ok) {
                if (cnt < KSEL && s > 0.f) {
                    out[(size_t)t * DO + myidx] = 1.0f;
                    s_lr[myidx] = t;
                }
            } else {
                fallback_row(X, W, bias, out, t, s_lr, s_s, s_x,
                             s_cand, s_cs, s_nc, s_chain, lane);
            }
            __syncwarp();
        }

        if (ch + 2 < NCH) { issue_chunk(ch + 2); CPA_WAIT1(); }
        else              { CPA_WAIT0(); }
        __syncwarp();
    }
}

// ---------------- launch ----------------------------------------------------
extern "C" void kernel_launch(void* const* d_in, const int* in_sizes, int n_in,
                              void* d_out, int out_size) {
    const float* X    = (const float*)d_in[0];
    const float* W    = (const float*)d_in[1];
    const float* bias = (const float*)d_in[2];
    float* out = (float*)d_out;

    const int n4 = NR * DO / 4;
    zero_kernel<<<(n4 + 255) / 256, 256>>>((float4*)out, n4);

    const size_t ncv = ((size_t)NR * DI + (size_t)DO * DI) / 4;
    cvt_kernel<<<(int)((ncv + 255) / 256), 256>>>(X, W);

    cudaFuncSetAttribute(gemm_hmma, cudaFuncAttributeMaxDynamicSharedMemorySize, GSMEM);
    dim3 gg(DO / 128, NR / 128);
    gemm_hmma<<<gg, 256, GSMEM>>>(bias);

    cand_kernel<<<NR, 256>>>();
    refine_kernel<<<NR, 1024>>>(X, W, bias);

    cudaFuncSetAttribute(seq_kernel, cudaFuncAttributeMaxDynamicSharedMemorySize, SEQ_SMEM);
    seq_kernel<<<1, 32, SEQ_SMEM>>>(X, W, bias, out);
}

// round 14
// speedup vs baseline: 1.0743x; 1.0474x over previous
#include <cuda_runtime.h>
#include <cuda_bf16.h>
#include <cstdint>
#include <cstddef>

#define NR 8192
#define DI 1024
#define DO 4096
#define C  32
#define KSEL 10
#define GAMMA_F 0.01618f
#define MARGIN 0.008f
#define FB_SLACK 0.03f
#define NEGINF (-3.4e38f)

#define B0ROWS 2048               // rows prepared before seq launches
#define GATE_CH (B0ROWS / 256)    // first chunk that needs the rest-flag

typedef unsigned long long ull;

// ---------------- static device scratch (no allocations allowed) ------------
__device__ __nv_bfloat16 g_xb[(size_t)NR * DI];   // 16 MB bf16 X
__device__ __nv_bfloat16 g_wb[(size_t)DO * DI];   //  8 MB bf16 W
__device__ float g_h[(size_t)NR * DO];            // 128 MB fp32 h (approx)
__device__ ull   g_cp[(size_t)NR * C];            // packed (h bits << 32) | idx
__device__ int   g_ci[NR * C];                    // candidate column indices
__device__ float g_cT[NR];                        // exact 33rd-largest approx h
__device__ int   g_ready;                         // rest-of-rows done flag

// ---------------- asm helpers ----------------------------------------------
__device__ __forceinline__ uint32_t s2u(const void* p) {
    uint32_t a;
    asm("{ .reg .u64 t; cvta.to.shared.u64 t, %1; cvt.u32.u64 %0, t; }"
        : "=r"(a) : "l"(p));
    return a;
}
__device__ __forceinline__ void cpa16(uint32_t s, const void* g) {
    asm volatile("cp.async.cg.shared.global [%0], [%1], 16;" :: "r"(s), "l"(g));
}
#define CPA_COMMIT() asm volatile("cp.async.commit_group;" ::: "memory")
#define CPA_WAIT1()  asm volatile("cp.async.wait_group 1;" ::: "memory")
#define CPA_WAIT0()  asm volatile("cp.async.wait_group 0;" ::: "memory")

__device__ __forceinline__ void ldsm4(uint32_t* r, uint32_t addr) {
    asm volatile("ldmatrix.sync.aligned.m8n8.x4.shared.b16 {%0,%1,%2,%3},[%4];"
                 : "=r"(r[0]), "=r"(r[1]), "=r"(r[2]), "=r"(r[3]) : "r"(addr));
}
__device__ __forceinline__ void mma16816(float* c, const uint32_t* a, const uint32_t* b) {
    asm volatile("mma.sync.aligned.m16n8k16.row.col.f32.bf16.bf16.f32 "
                 "{%0,%1,%2,%3},{%4,%5,%6,%7},{%8,%9},{%0,%1,%2,%3};"
                 : "+f"(c[0]), "+f"(c[1]), "+f"(c[2]), "+f"(c[3])
                 : "r"(a[0]), "r"(a[1]), "r"(a[2]), "r"(a[3]), "r"(b[0]), "r"(b[1]));
}

// ---------------- tiny flag kernels ----------------------------------------
__global__ void reset_kernel()   { g_ready = 0; __threadfence(); }
__global__ void setflag_kernel() { __threadfence(); g_ready = 1; }

// ---------------- Phase 0: zero output -------------------------------------
__global__ void zero_kernel(float4* __restrict__ p, int n4) {
    int i = blockIdx.x * blockDim.x + threadIdx.x;
    if (i < n4) p[i] = make_float4(0.f, 0.f, 0.f, 0.f);
}

// ---------------- Phase 0b: fp32 -> bf16 conversion ------------------------
__global__ void cvt_kernel(const float* __restrict__ X, const float* __restrict__ W) {
    const size_t NX4 = (size_t)NR * DI / 4;
    const size_t NW4 = (size_t)DO * DI / 4;
    size_t i = (size_t)blockIdx.x * blockDim.x + threadIdx.x;
    if (i >= NX4 + NW4) return;
    float4 v;
    uint2* dst;
    if (i < NX4) { v = ((const float4*)X)[i]; dst = (uint2*)g_xb + i; }
    else         { v = ((const float4*)W)[i - NX4]; dst = (uint2*)g_wb + (i - NX4); }
    uint32_t lo = (uint32_t)__bfloat16_as_ushort(__float2bfloat16_rn(v.x)) |
                  ((uint32_t)__bfloat16_as_ushort(__float2bfloat16_rn(v.y)) << 16);
    uint32_t hi = (uint32_t)__bfloat16_as_ushort(__float2bfloat16_rn(v.z)) |
                  ((uint32_t)__bfloat16_as_ushort(__float2bfloat16_rn(v.w)) << 16);
    *dst = make_uint2(lo, hi);
}

// ---------------- Phase 1: bf16 HMMA GEMM + bias + leaky -> fp32 h ---------
#define GBK 32
#define ROWB 80
#define TILEB (128 * ROWB)
#define STAGEB (2 * TILEB)
#define GSTAGES 3
#define GSMEM (GSTAGES * STAGEB)   // 61440

__global__ void __launch_bounds__(256, 1)
gemm_hmma(const float* __restrict__ bias, int rowbase) {
    extern __shared__ char sm[];
    const uint32_t sb = s2u(sm);
    const int tid = threadIdx.x;
    const int wid = tid >> 5, lane = tid & 31;
    const int row0 = rowbase + blockIdx.y * 128;
    const int col0 = blockIdx.x * 128;
    const int wm = wid & 1, wn = wid >> 1;

    auto load_stage = [&](int kt, int s) {
        const uint32_t sbase = sb + s * STAGEB;
#pragma unroll
        for (int i = 0; i < 4; ++i) {
            int item = tid + i * 256;
            int isB = item >> 9;
            int r = (item >> 2) & 127;
            int c = item & 3;
            uint32_t sa = sbase + isB * TILEB + r * ROWB + c * 16;
            const uint4* g = isB
                ? (const uint4*)g_wb + ((size_t)(col0 + r) * (DI / 8) + kt * 4 + c)
                : (const uint4*)g_xb + ((size_t)(row0 + r) * (DI / 8) + kt * 4 + c);
            cpa16(sa, g);
        }
        CPA_COMMIT();
    };

    float acc[4][4][4];
#pragma unroll
    for (int i = 0; i < 4; ++i)
#pragma unroll
        for (int j = 0; j < 4; ++j)
#pragma unroll
            for (int q = 0; q < 4; ++q) acc[i][j][q] = 0.f;

    const int NT = DI / GBK;
    load_stage(0, 0);
    load_stage(1, 1);
    CPA_WAIT1();
    __syncthreads();

#pragma unroll 1
    for (int kt = 0; kt < NT; ++kt) {
        const uint32_t Ab = sb + (kt % 3) * STAGEB;
        const uint32_t Bb = Ab + TILEB;

        uint32_t a[4][2][4], b[2][2][4];
        const int arow_l = lane & 15;
        const int asel   = (lane >> 4) & 1;
        const int g      = lane >> 3;
#pragma unroll
        for (int im = 0; im < 4; ++im)
#pragma unroll
            for (int ks = 0; ks < 2; ++ks) {
                int arow = wm * 64 + im * 16 + arow_l;
                int ach  = ks * 2 + asel;
                ldsm4(a[im][ks], Ab + arow * ROWB + ach * 16);
            }
#pragma unroll
        for (int p = 0; p < 2; ++p)
#pragma unroll
            for (int ks = 0; ks < 2; ++ks) {
                int blk = p * 2 + (g >> 1);
                int ch  = ks * 2 + (g & 1);
                int nrow = wn * 32 + blk * 8 + (lane & 7);
                ldsm4(b[p][ks], Bb + nrow * ROWB + ch * 16);
            }
#pragma unroll
        for (int im = 0; im < 4; ++im)
#pragma unroll
            for (int p = 0; p < 2; ++p)
#pragma unroll
                for (int ks = 0; ks < 2; ++ks) {
                    mma16816(acc[im][p * 2 + 0], a[im][ks], &b[p][ks][0]);
                    mma16816(acc[im][p * 2 + 1], a[im][ks], &b[p][ks][2]);
                }

        if (kt + 2 < NT) load_stage(kt + 2, (kt + 2) % 3);
        else             CPA_COMMIT();
        CPA_WAIT1();
        __syncthreads();
    }

    // epilogue: bias + leaky -> fp32 g_h, direct float2 stores
#pragma unroll
    for (int im = 0; im < 4; ++im)
#pragma unroll
        for (int in = 0; in < 4; ++in) {
            int rl = wm * 64 + im * 16 + (lane >> 2);
            int cl = wn * 32 + in * 8 + (lane & 3) * 2;
            float b0v = bias[col0 + cl], b1v = bias[col0 + cl + 1];
#pragma unroll
            for (int half = 0; half < 2; ++half) {
                float f0 = acc[im][in][half * 2 + 0] + b0v;
                float f1 = acc[im][in][half * 2 + 1] + b1v;
                f0 = f0 > 0.f ? f0 : 0.01f * f0;
                f1 = f1 > 0.f ? f1 : 0.01f * f1;
                float2* dst = (float2*)(g_h + (size_t)(row0 + rl + half * 8) * DO + col0 + cl);
                *dst = make_float2(f0, f1);
            }
        }
}

// ---------------- Phase 2: per-row top-32 candidates (exact fp32 radix) ----
__global__ void __launch_bounds__(256)
cand_kernel(int rowbase) {
    const int row = rowbase + blockIdx.x;
    const int tid = threadIdx.x;
    __shared__ unsigned skey[DO];    // 16 KB
    __shared__ unsigned hist[256];
    __shared__ unsigned s_pref;
    __shared__ int s_need, s_cnt;

    const float* h = g_h + (size_t)row * DO;
    for (int i = tid; i < DO; i += 256) {
        unsigned u = __float_as_uint(h[i]);
        u ^= (u >> 31) ? 0xFFFFFFFFu : 0x80000000u;   // monotone key
        skey[i] = u;
    }
    if (tid == 0) { s_pref = 0; s_need = C + 1; s_cnt = 0; }
    __syncthreads();

    for (int pass = 0; pass < 4; ++pass) {
        const int shift = 24 - 8 * pass;
        for (int i = tid; i < 256; i += 256) hist[i] = 0;
        __syncthreads();
        unsigned pref = s_pref;
        unsigned hm = (pass == 0) ? 0u : (0xFFFFFFFFu << (shift + 8));
        for (int i = tid; i < DO; i += 256) {
            unsigned k = skey[i];
            if (((k ^ pref) & hm) == 0) atomicAdd(&hist[(k >> shift) & 255], 1u);
        }
        __syncthreads();
        if (tid == 0) {
            int need = s_need, acc = 0, b = 255;
            for (; b >= 0; --b) { acc += (int)hist[b]; if (acc >= need) break; }
            if (b < 0) b = 0;                       // defensive (invariant holds)
            s_need = need - (acc - (int)hist[b]);
            s_pref = pref | ((unsigned)b << shift);
        }
        __syncthreads();
    }
    const unsigned K33 = s_pref;

    for (int i = tid; i < DO; i += 256) {
        if (skey[i] > K33) {
            int p = atomicAdd(&s_cnt, 1);
            if (p < C) g_ci[row * C + p] = i;       // defensive bound
        }
    }
    __syncthreads();
    for (int i = tid; i < DO; i += 256) {
        if (skey[i] == K33) {
            int p = atomicAdd(&s_cnt, 1);
            if (p < C) g_ci[row * C + p] = i;
        }
    }
    __syncthreads();
    if (tid < 32) {   // bitonic sort candidate indices ascending
        int v = g_ci[row * C + tid];
#pragma unroll
        for (int k2 = 2; k2 <= 32; k2 <<= 1)
#pragma unroll
            for (int j = k2 >> 1; j > 0; j >>= 1) {
                int pv = __shfl_xor_sync(0xFFFFFFFFu, v, j);
                bool up = ((tid & k2) == 0);
                bool takemin = (((tid & j) == 0) == up);
                int mn = v < pv ? v : pv, mx = v < pv ? pv : v;
                v = takemin ? mn : mx;
            }
        g_ci[row * C + tid] = v;
        if (tid == 0) {
            unsigned k = K33;
            g_cT[row] = __uint_as_float((k & 0x80000000u) ? (k ^ 0x80000000u) : ~k);
        }
    }
}

// ---------------- Phase 3: compensated-fp32 exact refinement ---------------
__global__ void __launch_bounds__(1024)
refine_kernel(const float* __restrict__ X, const float* __restrict__ W,
              const float* __restrict__ bias, int rowbase) {
    const int row = rowbase + blockIdx.x;
    const int tid = threadIdx.x;
    const int w = tid >> 5, lane = tid & 31;
    __shared__ float sx[DI];
    sx[tid] = X[(size_t)row * DI + tid];
    __syncthreads();

    const int ci = g_ci[row * C + w];
    const float* wr = W + (size_t)ci * DI;
    float hi = 0.f, lo = 0.f;
#pragma unroll 8
    for (int i = 0; i < DI / 32; ++i) {
        int kk = i * 32 + lane;
        float a = sx[kk], b = wr[kk];
        float p  = __fmul_rn(a, b);
        float pe = __fmaf_rn(a, b, -p);
        float t  = __fadd_rn(hi, p);
        float bp = __fsub_rn(t, hi);
        float e  = __fadd_rn(__fsub_rn(hi, __fsub_rn(t, bp)), __fsub_rn(p, bp));
        hi = t;
        lo = __fadd_rn(lo, __fadd_rn(e, pe));
    }
    double d = (double)hi + (double)lo;
#pragma unroll
    for (int off = 16; off; off >>= 1) d += __shfl_xor_sync(0xFFFFFFFFu, d, off);
    if (lane == 0) {
        float hv = (float)d;                 // correctly-rounded exact dot
        hv = __fadd_rn(hv, bias[ci]);
        hv = (hv > 0.f) ? hv : __fmul_rn(0.01f, hv);
        g_cp[(size_t)row * C + w] =
            ((ull)(unsigned)__float_as_uint(hv) << 32) | (unsigned)ci;
    }
}

// ---------------- Phase 4: sequential recurrence (one warp, smem-staged) ---
#define FB_CAP 512
#define CHR 256                          // rows per staged chunk
#define NCH (NR / CHR)                   // 32
#define CH_BYTES (CHR * C * 8)           // 65536 per buffer
#define CT_BYTES (CHR * 4)               // 1024 per buffer

// dynamic smem layout (bytes)
#define SM_LR    0
#define SM_SS    16384
#define SM_SX    32768
#define SM_CAND  36864
#define SM_CS    38912
#define SM_CHAIN 40960
#define SM_KEYS  41216
#define SM_NC    41344
#define SM_CBUF  41472
#define SM_CT    172544
#define SEQ_SMEM 174592

__device__ __noinline__ void fallback_row(const float* __restrict__ X,
                                          const float* __restrict__ W,
                                          const float* __restrict__ bias,
                                          float* __restrict__ out, int t,
                                          int* s_lr, float* s_s, float* s_x,
                                          int* s_cand, float* s_cs, int* s_nc,
                                          const float* s_chain, int lane) {
    // 1) approx s from fp32 h for all columns
    const float* hrow = g_h + (size_t)t * DO;
    for (int col = lane; col < DO; col += 32) {
        int age = t - s_lr[col] - 1; if (age > 63) age = 63;
        s_s[col] = hrow[col] * s_chain[age];
    }
    if (lane == 0) *s_nc = KSEL;      // slots 0..9 pre-seeded below
    __syncwarp();

    // 2) 10 arg-max rounds over smem; winner tombstoned + seeded into s_cand
    float t10b = NEGINF;
    for (int r = 0; r < KSEL; ++r) {
        float bv = NEGINF; int bi = lane;
        for (int i = lane; i < DO; i += 32) {
            float v = s_s[i];
            if (v > bv) { bv = v; bi = i; }
        }
        float lbv = bv; int lbi = bi;
#pragma unroll
        for (int off = 16; off; off >>= 1) {
            float ov = __shfl_xor_sync(0xFFFFFFFFu, bv, off);
            int   oi = __shfl_xor_sync(0xFFFFFFFFu, bi, off);
            if (ov > bv || (ov == bv && oi < bi)) { bv = ov; bi = oi; }
        }
        t10b = bv;
        if (lbi == bi && lbv == bv) {      // owner lane
            s_s[bi] = NEGINF;
            s_cand[r] = bi;
        }
        __syncwarp();
    }

    // 3) sound candidate set
    const float thr = t10b - FB_SLACK;
    for (int col = lane; col < DO; col += 32) {
        if (s_s[col] >= thr) {
            int p = atomicAdd(s_nc, 1);
            if (p < FB_CAP) s_cand[p] = col;
        }
    }
    __syncwarp();
    int nc = *s_nc; if (nc > FB_CAP) nc = FB_CAP;

    // X row to shared
    for (int i = lane; i < DI; i += 32) s_x[i] = X[(size_t)t * DI + i];
    __syncwarp();

    // 4) cooperative exact fp64 refine per candidate column (coalesced)
    for (int c = 0; c < nc; ++c) {
        const int col = s_cand[c];
        const float* wr = W + (size_t)col * DI;
        double d0 = 0, d1 = 0, d2 = 0, d3 = 0;
#pragma unroll 4
        for (int q = 0; q < DI / 32; q += 4) {
            d0 = fma((double)s_x[lane + 32 * (q + 0)], (double)wr[lane + 32 * (q + 0)], d0);
            d1 = fma((double)s_x[lane + 32 * (q + 1)], (double)wr[lane + 32 * (q + 1)], d1);
            d2 = fma((double)s_x[lane + 32 * (q + 2)], (double)wr[lane + 32 * (q + 2)], d2);
            d3 = fma((double)s_x[lane + 32 * (q + 3)], (double)wr[lane + 32 * (q + 3)], d3);
        }
        double d = (d0 + d1) + (d2 + d3);
#pragma unroll
        for (int off = 16; off; off >>= 1) d += __shfl_xor_sync(0xFFFFFFFFu, d, off);
        if (lane == 0) {
            float hv = (float)d;
            hv = __fadd_rn(hv, bias[col]);
            hv = hv > 0.f ? hv : __fmul_rn(0.01f, hv);
            int age = t - s_lr[col] - 1; if (age > 63) age = 63;
            s_cs[c] = __fmul_rn(hv, s_chain[age]);
        }
    }
    __syncwarp();

    // 5) exact top-10 (value desc, column asc tiebreak)
    for (int r = 0; r < KSEL; ++r) {
        float bv = NEGINF; int bcol = 1 << 30, bslot = 0;
        for (int c = lane; c < nc; c += 32) {
            float v = s_cs[c]; int col = s_cand[c];
            if (v > bv || (v == bv && col < bcol)) { bv = v; bcol = col; bslot = c; }
        }
#pragma unroll
        for (int off = 16; off; off >>= 1) {
            float ov = __shfl_xor_sync(0xFFFFFFFFu, bv, off);
            int   oc = __shfl_xor_sync(0xFFFFFFFFu, bcol, off);
            int   os = __shfl_xor_sync(0xFFFFFFFFu, bslot, off);
            if (ov > bv || (ov == bv && oc < bcol)) { bv = ov; bcol = oc; bslot = os; }
        }
        if (!(bv > 0.f)) break;
        if (lane == 0) {
            out[(size_t)t * DO + bcol] = 1.0f;
            s_lr[bcol] = t;
            s_cs[bslot] = NEGINF;
        }
        __syncwarp();
    }
    __syncwarp();
}

__global__ void __launch_bounds__(32)
seq_kernel(const float* __restrict__ X, const float* __restrict__ W,
           const float* __restrict__ bias, float* __restrict__ out) {
    extern __shared__ char dsm[];
    const uint32_t sb = s2u(dsm);
    int*      s_lr    = (int*)(dsm + SM_LR);
    float*    s_s     = (float*)(dsm + SM_SS);
    float*    s_x     = (float*)(dsm + SM_SX);
    int*      s_cand  = (int*)(dsm + SM_CAND);
    float*    s_cs    = (float*)(dsm + SM_CS);
    float*    s_chain = (float*)(dsm + SM_CHAIN);
    unsigned* s_keys  = (unsigned*)(dsm + SM_KEYS);
    int*      s_nc    = (int*)(dsm + SM_NC);
    const int lane = threadIdx.x;

    for (int i = lane; i < DO; i += 32) s_lr[i] = -1000000;
    if (lane == 0) {
        float c = 0.f;
        s_chain[0] = 0.f;
        for (int i = 1; i < 64; ++i) {
            c = fminf(__fadd_rn(c, GAMMA_F), 1.0f);
            s_chain[i] = c;
        }
    }
    __syncwarp();

    // chunk loader: stage 256 rows of packed candidates + thresholds to smem
    auto issue_chunk = [&](int ch) {
        const char* gsrc = (const char*)g_cp + (size_t)ch * CH_BYTES;
        uint32_t sdst = sb + SM_CBUF + (ch & 1) * CH_BYTES;
        for (int i = 0; i < CH_BYTES / 512; ++i)
            cpa16(sdst + lane * 16 + i * 512, gsrc + lane * 16 + i * 512);
        const char* gct = (const char*)g_cT + (size_t)ch * CT_BYTES;
        uint32_t sct = sb + SM_CT + (ch & 1) * CT_BYTES;
        cpa16(sct + lane * 16, gct + lane * 16);
        cpa16(sct + 512 + lane * 16, gct + 512 + lane * 16);
        CPA_COMMIT();
    };

    issue_chunk(0);
    issue_chunk(1);
    CPA_WAIT1();
    __syncwarp();

    for (int ch = 0; ch < NCH; ++ch) {
        const char* cbuf = dsm + SM_CBUF + (ch & 1) * CH_BYTES;
        const char* ctb  = dsm + SM_CT   + (ch & 1) * CT_BYTES;

        for (int r = 0; r < CHR; ++r) {
            const int t = ch * CHR + r;
            const ull pk  = *(const ull*)(cbuf + r * (C * 8) + lane * 8);
            const float T = *(const float*)(ctb + r * 4);
            const int   myidx = (int)(pk & 0xFFFFFFFFu);
            const float myh   = __uint_as_float((unsigned)(pk >> 32));

            int lr = s_lr[myidx];
            int age = t - lr - 1; if (age > 63) age = 63;
            float s = __fmul_rn(myh, s_chain[age]);
            if (s == 0.0f) s = 0.0f;          // canonicalize -0.0 -> +0.0

            unsigned u = __float_as_uint(s);
            u ^= (u >> 31) ? 0xFFFFFFFFu : 0x80000000u;
            s_keys[lane] = u;
            __syncwarp();

            int cnt = 0;
#pragma unroll
            for (int j = 0; j < 8; ++j) {
                uint4 k = *(const uint4*)&s_keys[4 * j];
                cnt += (k.x > u) || (k.x == u && (4 * j + 0) < lane);
                cnt += (k.y > u) || (k.y == u && (4 * j + 1) < lane);
                cnt += (k.z > u) || (k.z == u && (4 * j + 2) < lane);
                cnt += (k.w > u) || (k.w == u && (4 * j + 3) < lane);
            }
            unsigned m9 = __ballot_sync(0xFFFFFFFFu, cnt == 9);
            float v10 = __shfl_sync(0xFFFFFFFFu, s, m9 ? (__ffs(m9) - 1) : 0);
            bool ok = m9 && (v10 > T + MARGIN);

            if (ok) {
                if (cnt < KSEL && s > 0.f) {
                    out[(size_t)t * DO + myidx] = 1.0f;
                    s_lr[myidx] = t;
                }
            } else {
                fallback_row(X, W, bias, out, t, s_lr, s_s, s_x,
                             s_cand, s_cs, s_nc, s_chain, lane);
            }
            __syncwarp();
        }

        if (ch + 2 < NCH) {
            if (ch + 2 == GATE_CH) {       // first rest-block chunk: wait flag
                if (lane == 0) while (((volatile int*)&g_ready)[0] == 0) {}
                __syncwarp();
            }
            issue_chunk(ch + 2);
            CPA_WAIT1();
        } else {
            CPA_WAIT0();
        }
        __syncwarp();
    }
}

// ---------------- launch ----------------------------------------------------
extern "C" void kernel_launch(void* const* d_in, const int* in_sizes, int n_in,
                              void* d_out, int out_size) {
    const float* X    = (const float*)d_in[0];
    const float* W    = (const float*)d_in[1];
    const float* bias = (const float*)d_in[2];
    float* out = (float*)d_out;

    cudaFuncSetAttribute(gemm_hmma, cudaFuncAttributeMaxDynamicSharedMemorySize, GSMEM);
    cudaFuncSetAttribute(seq_kernel, cudaFuncAttributeMaxDynamicSharedMemorySize, SEQ_SMEM);

    // second stream + fork/join events (host-side objects; created per call,
    // intentionally not destroyed during capture — bounded, harness calls few)
    cudaStream_t s2;
    cudaEvent_t evF, evJ;
    cudaStreamCreateWithFlags(&s2, cudaStreamNonBlocking);
    cudaEventCreateWithFlags(&evF, cudaEventDisableTiming);
    cudaEventCreateWithFlags(&evJ, cudaEventDisableTiming);

    // ---- legacy stream: prepare first B0ROWS rows, then run seq ----
    reset_kernel<<<1, 1>>>();

    const int n4 = NR * DO / 4;
    zero_kernel<<<(n4 + 255) / 256, 256>>>((float4*)out, n4);

    const size_t ncv = ((size_t)NR * DI + (size_t)DO * DI) / 4;
    cvt_kernel<<<(int)((ncv + 255) / 256), 256>>>(X, W);

    gemm_hmma<<<dim3(DO / 128, B0ROWS / 128), 256, GSMEM>>>(bias, 0);
    cand_kernel<<<B0ROWS, 256>>>(0);
    refine_kernel<<<B0ROWS, 1024>>>(X, W, bias, 0);

    cudaEventRecord(evF, 0);

    // ---- forked stream: prepare remaining rows concurrently with seq ----
    cudaStreamWaitEvent(s2, evF, 0);
    gemm_hmma<<<dim3(DO / 128, (NR - B0ROWS) / 128), 256, GSMEM, s2>>>(bias, B0ROWS);
    cand_kernel<<<NR - B0ROWS, 256, 0, s2>>>(B0ROWS);
    refine_kernel<<<NR - B0ROWS, 1024, 0, s2>>>(X, W, bias, B0ROWS);
    setflag_kernel<<<1, 1, 0, s2>>>();
    cudaEventRecord(evJ, s2);

    // ---- seq runs concurrently with the forked branch ----
    seq_kernel<<<1, 32, SEQ_SMEM>>>(X, W, bias, out);

    // join the fork back into the captured stream
    cudaStreamWaitEvent(0, evJ, 0);
}

// round 15
// speedup vs baseline: 1.0919x; 1.0164x over previous
#include <cuda_runtime.h>
#include <cuda_bf16.h>
#include <cstdint>
#include <cstddef>

#define NR 8192
#define DI 1024
#define DO 4096
#define C  32
#define KSEL 10
#define GAMMA_F 0.01618f
#define MARGIN 0.008f
#define FB_SLACK 0.03f
#define NEGINF (-3.4e38f)

#define B0ROWS 512                // rows prepared before seq launches
#define MIDROWS 4096              // stage-1 flag covers rows [B0ROWS, MIDROWS)

typedef unsigned long long ull;

// ---------------- static device scratch (no allocations allowed) ------------
__device__ __nv_bfloat16 g_xb[(size_t)NR * DI];   // 16 MB bf16 X
__device__ __nv_bfloat16 g_wb[(size_t)DO * DI];   //  8 MB bf16 W
__device__ float g_h[(size_t)NR * DO];            // 128 MB fp32 h (approx)
__device__ ull   g_cp[(size_t)NR * C];            // packed (h bits << 32) | idx
__device__ int   g_ci[NR * C];                    // candidate column indices
__device__ float g_cT[NR];                        // exact 33rd-largest approx h
__device__ int   g_ready;                         // staged-completion counter

// ---------------- asm helpers ----------------------------------------------
__device__ __forceinline__ uint32_t s2u(const void* p) {
    uint32_t a;
    asm("{ .reg .u64 t; cvta.to.shared.u64 t, %1; cvt.u32.u64 %0, t; }"
        : "=r"(a) : "l"(p));
    return a;
}
__device__ __forceinline__ void cpa16(uint32_t s, const void* g) {
    asm volatile("cp.async.cg.shared.global [%0], [%1], 16;" :: "r"(s), "l"(g));
}
#define CPA_COMMIT() asm volatile("cp.async.commit_group;" ::: "memory")
#define CPA_WAIT1()  asm volatile("cp.async.wait_group 1;" ::: "memory")
#define CPA_WAIT0()  asm volatile("cp.async.wait_group 0;" ::: "memory")

__device__ __forceinline__ void ldsm4(uint32_t* r, uint32_t addr) {
    asm volatile("ldmatrix.sync.aligned.m8n8.x4.shared.b16 {%0,%1,%2,%3},[%4];"
                 : "=r"(r[0]), "=r"(r[1]), "=r"(r[2]), "=r"(r[3]) : "r"(addr));
}
__device__ __forceinline__ void mma16816(float* c, const uint32_t* a, const uint32_t* b) {
    asm volatile("mma.sync.aligned.m16n8k16.row.col.f32.bf16.bf16.f32 "
                 "{%0,%1,%2,%3},{%4,%5,%6,%7},{%8,%9},{%0,%1,%2,%3};"
                 : "+f"(c[0]), "+f"(c[1]), "+f"(c[2]), "+f"(c[3])
                 : "r"(a[0]), "r"(a[1]), "r"(a[2]), "r"(a[3]), "r"(b[0]), "r"(b[1]));
}

// ---------------- tiny flag kernels ----------------------------------------
__global__ void reset_kernel()   { g_ready = 0; __threadfence(); }
__global__ void setflag_kernel() { __threadfence(); atomicAdd(&g_ready, 1); }

// ---------------- Phase 0: zero a slice of the output -----------------------
__global__ void zero_kernel(float4* __restrict__ p, int n4) {
    int i = blockIdx.x * blockDim.x + threadIdx.x;
    if (i < n4) p[i] = make_float4(0.f, 0.f, 0.f, 0.f);
}

// ---------------- Phase 0b: fp32 -> bf16 conversion ------------------------
__global__ void cvt_kernel(const float* __restrict__ X, const float* __restrict__ W) {
    const size_t NX4 = (size_t)NR * DI / 4;
    const size_t NW4 = (size_t)DO * DI / 4;
    size_t i = (size_t)blockIdx.x * blockDim.x + threadIdx.x;
    if (i >= NX4 + NW4) return;
    float4 v;
    uint2* dst;
    if (i < NX4) { v = ((const float4*)X)[i]; dst = (uint2*)g_xb + i; }
    else         { v = ((const float4*)W)[i - NX4]; dst = (uint2*)g_wb + (i - NX4); }
    uint32_t lo = (uint32_t)__bfloat16_as_ushort(__float2bfloat16_rn(v.x)) |
                  ((uint32_t)__bfloat16_as_ushort(__float2bfloat16_rn(v.y)) << 16);
    uint32_t hi = (uint32_t)__bfloat16_as_ushort(__float2bfloat16_rn(v.z)) |
                  ((uint32_t)__bfloat16_as_ushort(__float2bfloat16_rn(v.w)) << 16);
    *dst = make_uint2(lo, hi);
}

// ---------------- Phase 1: bf16 HMMA GEMM + bias + leaky -> fp32 h ---------
#define GBK 32
#define ROWB 80
#define TILEB (128 * ROWB)
#define STAGEB (2 * TILEB)
#define GSTAGES 3
#define GSMEM (GSTAGES * STAGEB)   // 61440

__global__ void __launch_bounds__(256, 1)
gemm_hmma(const float* __restrict__ bias, int rowbase) {
    extern __shared__ char sm[];
    const uint32_t sb = s2u(sm);
    const int tid = threadIdx.x;
    const int wid = tid >> 5, lane = tid & 31;
    const int row0 = rowbase + blockIdx.y * 128;
    const int col0 = blockIdx.x * 128;
    const int wm = wid & 1, wn = wid >> 1;

    auto load_stage = [&](int kt, int s) {
        const uint32_t sbase = sb + s * STAGEB;
#pragma unroll
        for (int i = 0; i < 4; ++i) {
            int item = tid + i * 256;
            int isB = item >> 9;
            int r = (item >> 2) & 127;
            int c = item & 3;
            uint32_t sa = sbase + isB * TILEB + r * ROWB + c * 16;
            const uint4* g = isB
                ? (const uint4*)g_wb + ((size_t)(col0 + r) * (DI / 8) + kt * 4 + c)
                : (const uint4*)g_xb + ((size_t)(row0 + r) * (DI / 8) + kt * 4 + c);
            cpa16(sa, g);
        }
        CPA_COMMIT();
    };

    float acc[4][4][4];
#pragma unroll
    for (int i = 0; i < 4; ++i)
#pragma unroll
        for (int j = 0; j < 4; ++j)
#pragma unroll
            for (int q = 0; q < 4; ++q) acc[i][j][q] = 0.f;

    const int NT = DI / GBK;
    load_stage(0, 0);
    load_stage(1, 1);
    CPA_WAIT1();
    __syncthreads();

#pragma unroll 1
    for (int kt = 0; kt < NT; ++kt) {
        const uint32_t Ab = sb + (kt % 3) * STAGEB;
        const uint32_t Bb = Ab + TILEB;

        uint32_t a[4][2][4], b[2][2][4];
        const int arow_l = lane & 15;
        const int asel   = (lane >> 4) & 1;
        const int g      = lane >> 3;
#pragma unroll
        for (int im = 0; im < 4; ++im)
#pragma unroll
            for (int ks = 0; ks < 2; ++ks) {
                int arow = wm * 64 + im * 16 + arow_l;
                int ach  = ks * 2 + asel;
                ldsm4(a[im][ks], Ab + arow * ROWB + ach * 16);
            }
#pragma unroll
        for (int p = 0; p < 2; ++p)
#pragma unroll
            for (int ks = 0; ks < 2; ++ks) {
                int blk = p * 2 + (g >> 1);
                int ch  = ks * 2 + (g & 1);
                int nrow = wn * 32 + blk * 8 + (lane & 7);
                ldsm4(b[p][ks], Bb + nrow * ROWB + ch * 16);
            }
#pragma unroll
        for (int im = 0; im < 4; ++im)
#pragma unroll
            for (int p = 0; p < 2; ++p)
#pragma unroll
                for (int ks = 0; ks < 2; ++ks) {
                    mma16816(acc[im][p * 2 + 0], a[im][ks], &b[p][ks][0]);
                    mma16816(acc[im][p * 2 + 1], a[im][ks], &b[p][ks][2]);
                }

        if (kt + 2 < NT) load_stage(kt + 2, (kt + 2) % 3);
        else             CPA_COMMIT();
        CPA_WAIT1();
        __syncthreads();
    }

    // epilogue: bias + leaky -> fp32 g_h, direct float2 stores
#pragma unroll
    for (int im = 0; im < 4; ++im)
#pragma unroll
        for (int in = 0; in < 4; ++in) {
            int rl = wm * 64 + im * 16 + (lane >> 2);
            int cl = wn * 32 + in * 8 + (lane & 3) * 2;
            float b0v = bias[col0 + cl], b1v = bias[col0 + cl + 1];
#pragma unroll
            for (int half = 0; half < 2; ++half) {
                float f0 = acc[im][in][half * 2 + 0] + b0v;
                float f1 = acc[im][in][half * 2 + 1] + b1v;
                f0 = f0 > 0.f ? f0 : 0.01f * f0;
                f1 = f1 > 0.f ? f1 : 0.01f * f1;
                float2* dst = (float2*)(g_h + (size_t)(row0 + rl + half * 8) * DO + col0 + cl);
                *dst = make_float2(f0, f1);
            }
        }
}

// ---------------- Phase 2: per-row top-32 candidates (exact fp32 radix) ----
__global__ void __launch_bounds__(256)
cand_kernel(int rowbase) {
    const int row = rowbase + blockIdx.x;
    const int tid = threadIdx.x;
    __shared__ unsigned skey[DO];    // 16 KB
    __shared__ unsigned hist[256];
    __shared__ unsigned s_pref;
    __shared__ int s_need, s_cnt;

    const float* h = g_h + (size_t)row * DO;
    for (int i = tid; i < DO; i += 256) {
        unsigned u = __float_as_uint(h[i]);
        u ^= (u >> 31) ? 0xFFFFFFFFu : 0x80000000u;   // monotone key
        skey[i] = u;
    }
    if (tid == 0) { s_pref = 0; s_need = C + 1; s_cnt = 0; }
    __syncthreads();

    for (int pass = 0; pass < 4; ++pass) {
        const int shift = 24 - 8 * pass;
        for (int i = tid; i < 256; i += 256) hist[i] = 0;
        __syncthreads();
        unsigned pref = s_pref;
        unsigned hm = (pass == 0) ? 0u : (0xFFFFFFFFu << (shift + 8));
        for (int i = tid; i < DO; i += 256) {
            unsigned k = skey[i];
            if (((k ^ pref) & hm) == 0) atomicAdd(&hist[(k >> shift) & 255], 1u);
        }
        __syncthreads();
        if (tid == 0) {
            int need = s_need, acc = 0, b = 255;
            for (; b >= 0; --b) { acc += (int)hist[b]; if (acc >= need) break; }
            if (b < 0) b = 0;                       // defensive (invariant holds)
            s_need = need - (acc - (int)hist[b]);
            s_pref = pref | ((unsigned)b << shift);
        }
        __syncthreads();
    }
    const unsigned K33 = s_pref;

    for (int i = tid; i < DO; i += 256) {
        if (skey[i] > K33) {
            int p = atomicAdd(&s_cnt, 1);
            if (p < C) g_ci[row * C + p] = i;       // defensive bound
        }
    }
    __syncthreads();
    for (int i = tid; i < DO; i += 256) {
        if (skey[i] == K33) {
            int p = atomicAdd(&s_cnt, 1);
            if (p < C) g_ci[row * C + p] = i;
        }
    }
    __syncthreads();
    if (tid < 32) {   // bitonic sort candidate indices ascending
        int v = g_ci[row * C + tid];
#pragma unroll
        for (int k2 = 2; k2 <= 32; k2 <<= 1)
#pragma unroll
            for (int j = k2 >> 1; j > 0; j >>= 1) {
                int pv = __shfl_xor_sync(0xFFFFFFFFu, v, j);
                bool up = ((tid & k2) == 0);
                bool takemin = (((tid & j) == 0) == up);
                int mn = v < pv ? v : pv, mx = v < pv ? pv : v;
                v = takemin ? mn : mx;
            }
        g_ci[row * C + tid] = v;
        if (tid == 0) {
            unsigned k = K33;
            g_cT[row] = __uint_as_float((k & 0x80000000u) ? (k ^ 0x80000000u) : ~k);
        }
    }
}

// ---------------- Phase 3: compensated-fp32 exact refinement ---------------
__global__ void __launch_bounds__(1024)
refine_kernel(const float* __restrict__ X, const float* __restrict__ W,
              const float* __restrict__ bias, int rowbase) {
    const int row = rowbase + blockIdx.x;
    const int tid = threadIdx.x;
    const int w = tid >> 5, lane = tid & 31;
    __shared__ float sx[DI];
    sx[tid] = X[(size_t)row * DI + tid];
    __syncthreads();

    const int ci = g_ci[row * C + w];
    const float* wr = W + (size_t)ci * DI;
    float hi = 0.f, lo = 0.f;
#pragma unroll 8
    for (int i = 0; i < DI / 32; ++i) {
        int kk = i * 32 + lane;
        float a = sx[kk], b = wr[kk];
        float p  = __fmul_rn(a, b);
        float pe = __fmaf_rn(a, b, -p);
        float t  = __fadd_rn(hi, p);
        float bp = __fsub_rn(t, hi);
        float e  = __fadd_rn(__fsub_rn(hi, __fsub_rn(t, bp)), __fsub_rn(p, bp));
        hi = t;
        lo = __fadd_rn(lo, __fadd_rn(e, pe));
    }
    double d = (double)hi + (double)lo;
#pragma unroll
    for (int off = 16; off; off >>= 1) d += __shfl_xor_sync(0xFFFFFFFFu, d, off);
    if (lane == 0) {
        float hv = (float)d;                 // correctly-rounded exact dot
        hv = __fadd_rn(hv, bias[ci]);
        hv = (hv > 0.f) ? hv : __fmul_rn(0.01f, hv);
        g_cp[(size_t)row * C + w] =
            ((ull)(unsigned)__float_as_uint(hv) << 32) | (unsigned)ci;
    }
}

// ---------------- Phase 4: sequential recurrence (one warp, smem-staged) ---
#define FB_CAP 512
#define CHR 256
#define NCH (NR / CHR)                   // 32
#define CH_BYTES (CHR * C * 8)           // 65536
#define CT_BYTES (CHR * 4)               // 1024
#define GATE1_CH (B0ROWS / CHR)          // 2  (needs flag>=1)
#define GATE2_CH (MIDROWS / CHR)         // 16 (needs flag>=2)

// dynamic smem layout (bytes)
#define SM_LR    0
#define SM_SS    16384
#define SM_SX    32768
#define SM_CAND  36864
#define SM_CS    38912
#define SM_CHAIN 40960
#define SM_KEYS  41216
#define SM_NC    41344
#define SM_CBUF  41472
#define SM_CT    172544
#define SEQ_SMEM 174592

__device__ __noinline__ void fallback_row(const float* __restrict__ X,
                                          const float* __restrict__ W,
                                          const float* __restrict__ bias,
                                          float* __restrict__ out, int t,
                                          int* s_lr, float* s_s, float* s_x,
                                          int* s_cand, float* s_cs, int* s_nc,
                                          const float* s_chain, int lane) {
    // 1) approx s from fp32 h for all columns
    const float* hrow = g_h + (size_t)t * DO;
    for (int col = lane; col < DO; col += 32) {
        int age = t - s_lr[col] - 1; if (age > 63) age = 63;
        s_s[col] = hrow[col] * s_chain[age];
    }
    if (lane == 0) *s_nc = KSEL;
    __syncwarp();

    // 2) 10 arg-max rounds over smem; winner tombstoned + seeded into s_cand
    float t10b = NEGINF;
    for (int r = 0; r < KSEL; ++r) {
        float bv = NEGINF; int bi = lane;
        for (int i = lane; i < DO; i += 32) {
            float v = s_s[i];
            if (v > bv) { bv = v; bi = i; }
        }
        float lbv = bv; int lbi = bi;
#pragma unroll
        for (int off = 16; off; off >>= 1) {
            float ov = __shfl_xor_sync(0xFFFFFFFFu, bv, off);
            int   oi = __shfl_xor_sync(0xFFFFFFFFu, bi, off);
            if (ov > bv || (ov == bv && oi < bi)) { bv = ov; bi = oi; }
        }
        t10b = bv;
        if (lbi == bi && lbv == bv) {      // owner lane
            s_s[bi] = NEGINF;
            s_cand[r] = bi;
        }
        __syncwarp();
    }

    // 3) sound candidate set
    const float thr = t10b - FB_SLACK;
    for (int col = lane; col < DO; col += 32) {
        if (s_s[col] >= thr) {
            int p = atomicAdd(s_nc, 1);
            if (p < FB_CAP) s_cand[p] = col;
        }
    }
    __syncwarp();
    int nc = *s_nc; if (nc > FB_CAP) nc = FB_CAP;

    // X row to shared
    for (int i = lane; i < DI; i += 32) s_x[i] = X[(size_t)t * DI + i];
    __syncwarp();

    // 4) cooperative exact fp64 refine per candidate column (coalesced)
    for (int c = 0; c < nc; ++c) {
        const int col = s_cand[c];
        const float* wr = W + (size_t)col * DI;
        double d0 = 0, d1 = 0, d2 = 0, d3 = 0;
#pragma unroll 4
        for (int q = 0; q < DI / 32; q += 4) {
            d0 = fma((double)s_x[lane + 32 * (q + 0)], (double)wr[lane + 32 * (q + 0)], d0);
            d1 = fma((double)s_x[lane + 32 * (q + 1)], (double)wr[lane + 32 * (q + 1)], d1);
            d2 = fma((double)s_x[lane + 32 * (q + 2)], (double)wr[lane + 32 * (q + 2)], d2);
            d3 = fma((double)s_x[lane + 32 * (q + 3)], (double)wr[lane + 32 * (q + 3)], d3);
        }
        double d = (d0 + d1) + (d2 + d3);
#pragma unroll
        for (int off = 16; off; off >>= 1) d += __shfl_xor_sync(0xFFFFFFFFu, d, off);
        if (lane == 0) {
            float hv = (float)d;
            hv = __fadd_rn(hv, bias[col]);
            hv = hv > 0.f ? hv : __fmul_rn(0.01f, hv);
            int age = t - s_lr[col] - 1; if (age > 63) age = 63;
            s_cs[c] = __fmul_rn(hv, s_chain[age]);
        }
    }
    __syncwarp();

    // 5) exact top-10 (value desc, column asc tiebreak)
    for (int r = 0; r < KSEL; ++r) {
        float bv = NEGINF; int bcol = 1 << 30, bslot = 0;
        for (int c = lane; c < nc; c += 32) {
            float v = s_cs[c]; int col = s_cand[c];
            if (v > bv || (v == bv && col < bcol)) { bv = v; bcol = col; bslot = c; }
        }
#pragma unroll
        for (int off = 16; off; off >>= 1) {
            float ov = __shfl_xor_sync(0xFFFFFFFFu, bv, off);
            int   oc = __shfl_xor_sync(0xFFFFFFFFu, bcol, off);
            int   os = __shfl_xor_sync(0xFFFFFFFFu, bslot, off);
            if (ov > bv || (ov == bv && oc < bcol)) { bv = ov; bcol = oc; bslot = os; }
        }
        if (!(bv > 0.f)) break;
        if (lane == 0) {
            out[(size_t)t * DO + bcol] = 1.0f;
            s_lr[bcol] = t;
            s_cs[bslot] = NEGINF;
        }
        __syncwarp();
    }
    __syncwarp();
}

__global__ void __launch_bounds__(32)
seq_kernel(const float* __restrict__ X, const float* __restrict__ W,
           const float* __restrict__ bias, float* __restrict__ out) {
    extern __shared__ char dsm[];
    const uint32_t sb = s2u(dsm);
    int*      s_lr    = (int*)(dsm + SM_LR);
    float*    s_s     = (float*)(dsm + SM_SS);
    float*    s_x     = (float*)(dsm + SM_SX);
    int*      s_cand  = (int*)(dsm + SM_CAND);
    float*    s_cs    = (float*)(dsm + SM_CS);
    float*    s_chain = (float*)(dsm + SM_CHAIN);
    unsigned* s_keys  = (unsigned*)(dsm + SM_KEYS);
    int*      s_nc    = (int*)(dsm + SM_NC);
    const int lane = threadIdx.x;

    for (int i = lane; i < DO; i += 32) s_lr[i] = -1000000;
    if (lane == 0) {
        float c = 0.f;
        s_chain[0] = 0.f;
        for (int i = 1; i < 64; ++i) {
            c = fminf(__fadd_rn(c, GAMMA_F), 1.0f);
            s_chain[i] = c;
        }
    }
    __syncwarp();

    // chunk loader: stage 256 rows of packed candidates + thresholds to smem
    auto issue_chunk = [&](int ch) {
        const char* gsrc = (const char*)g_cp + (size_t)ch * CH_BYTES;
        uint32_t sdst = sb + SM_CBUF + (ch & 1) * CH_BYTES;
        for (int i = 0; i < CH_BYTES / 512; ++i)
            cpa16(sdst + lane * 16 + i * 512, gsrc + lane * 16 + i * 512);
        const char* gct = (const char*)g_cT + (size_t)ch * CT_BYTES;
        uint32_t sct = sb + SM_CT + (ch & 1) * CT_BYTES;
        cpa16(sct + lane * 16, gct + lane * 16);
        cpa16(sct + 512 + lane * 16, gct + 512 + lane * 16);
        CPA_COMMIT();
    };

    issue_chunk(0);
    issue_chunk(1);
    CPA_WAIT1();
    __syncwarp();

    for (int ch = 0; ch < NCH; ++ch) {
        const char* cbuf = dsm + SM_CBUF + (ch & 1) * CH_BYTES;
        const char* ctb  = dsm + SM_CT   + (ch & 1) * CT_BYTES;

        for (int r = 0; r < CHR; ++r) {
            const int t = ch * CHR + r;
            const ull pk  = *(const ull*)(cbuf + r * (C * 8) + lane * 8);
            const float T = *(const float*)(ctb + r * 4);
            const int   myidx = (int)(pk & 0xFFFFFFFFu);
            const float myh   = __uint_as_float((unsigned)(pk >> 32));

            int lr = s_lr[myidx];
            int age = t - lr - 1; if (age > 63) age = 63;
            float s = __fmul_rn(myh, s_chain[age]);
            if (s == 0.0f) s = 0.0f;          // canonicalize -0.0 -> +0.0

            unsigned u = __float_as_uint(s);
            u ^= (u >> 31) ? 0xFFFFFFFFu : 0x80000000u;
            s_keys[lane] = u;
            __syncwarp();

            int cnt = 0;
#pragma unroll
            for (int j = 0; j < 8; ++j) {
                uint4 k = *(const uint4*)&s_keys[4 * j];
                cnt += (k.x > u) || (k.x == u && (4 * j + 0) < lane);
                cnt += (k.y > u) || (k.y == u && (4 * j + 1) < lane);
                cnt += (k.z > u) || (k.z == u && (4 * j + 2) < lane);
                cnt += (k.w > u) || (k.w == u && (4 * j + 3) < lane);
            }
            unsigned m9 = __ballot_sync(0xFFFFFFFFu, cnt == 9);
            float v10 = __shfl_sync(0xFFFFFFFFu, s, m9 ? (__ffs(m9) - 1) : 0);
            bool ok = m9 && (v10 > T + MARGIN);

            if (ok) {
                if (cnt < KSEL && s > 0.f) {
                    out[(size_t)t * DO + myidx] = 1.0f;
                    s_lr[myidx] = t;
                }
            } else {
                fallback_row(X, W, bias, out, t, s_lr, s_s, s_x,
                             s_cand, s_cs, s_nc, s_chain, lane);
            }
            __syncwarp();
        }

        if (ch + 2 < NCH) {
            const int nxt = ch + 2;
            if (nxt == GATE1_CH) {         // rows [512,4096): need flag >= 1
                if (lane == 0) while (((volatile int*)&g_ready)[0] < 1) {}
                __syncwarp();
            }
            if (nxt == GATE2_CH) {         // rows [4096,8192): need flag >= 2
                if (lane == 0) while (((volatile int*)&g_ready)[0] < 2) {}
                __syncwarp();
            }
            issue_chunk(nxt);
            CPA_WAIT1();
        } else {
            CPA_WAIT0();
        }
        __syncwarp();
    }
}

// ---------------- launch ----------------------------------------------------
extern "C" void kernel_launch(void* const* d_in, const int* in_sizes, int n_in,
                              void* d_out, int out_size) {
    const float* X    = (const float*)d_in[0];
    const float* W    = (const float*)d_in[1];
    const float* bias = (const float*)d_in[2];
    float* out = (float*)d_out;

    cudaFuncSetAttribute(gemm_hmma, cudaFuncAttributeMaxDynamicSharedMemorySize, GSMEM);
    cudaFuncSetAttribute(seq_kernel, cudaFuncAttributeMaxDynamicSharedMemorySize, SEQ_SMEM);

    cudaStream_t s2;
    cudaEvent_t evF, evJ;
    cudaStreamCreateWithFlags(&s2, cudaStreamNonBlocking);
    cudaEventCreateWithFlags(&evF, cudaEventDisableTiming);
    cudaEventCreateWithFlags(&evJ, cudaEventDisableTiming);

    // ---- legacy stream: minimal serial prefix for rows [0, B0ROWS) ----
    reset_kernel<<<1, 1>>>();

    const int b0n4 = B0ROWS * DO / 4;
    zero_kernel<<<(b0n4 + 255) / 256, 256>>>((float4*)out, b0n4);

    const size_t ncv = ((size_t)NR * DI + (size_t)DO * DI) / 4;
    cvt_kernel<<<(int)((ncv + 255) / 256), 256>>>(X, W);

    cudaEventRecord(evF, 0);             // fork point: after cvt

    gemm_hmma<<<dim3(DO / 128, B0ROWS / 128), 256, GSMEM>>>(bias, 0);
    cand_kernel<<<B0ROWS, 256>>>(0);
    refine_kernel<<<B0ROWS, 1024>>>(X, W, bias, 0);

    // ---- forked stream: rest of rows in two flagged stages ----
    cudaStreamWaitEvent(s2, evF, 0);
    const int restn4 = (NR - B0ROWS) * DO / 4;
    zero_kernel<<<(restn4 + 255) / 256, 256, 0, s2>>>(
        (float4*)(out + (size_t)B0ROWS * DO), restn4);

    // stage 1: rows [B0ROWS, MIDROWS)
    gemm_hmma<<<dim3(DO / 128, (MIDROWS - B0ROWS) / 128), 256, GSMEM, s2>>>(bias, B0ROWS);
    cand_kernel<<<MIDROWS - B0ROWS, 256, 0, s2>>>(B0ROWS);
    refine_kernel<<<MIDROWS - B0ROWS, 1024, 0, s2>>>(X, W, bias, B0ROWS);
    setflag_kernel<<<1, 1, 0, s2>>>();

    // stage 2: rows [MIDROWS, NR)
    gemm_hmma<<<dim3(DO / 128, (NR - MIDROWS) / 128), 256, GSMEM, s2>>>(bias, MIDROWS);
    cand_kernel<<<NR - MIDROWS, 256, 0, s2>>>(MIDROWS);
    refine_kernel<<<NR - MIDROWS, 1024, 0, s2>>>(X, W, bias, MIDROWS);
    setflag_kernel<<<1, 1, 0, s2>>>();
    cudaEventRecord(evJ, s2);

    // ---- seq runs concurrently with the forked branch ----
    seq_kernel<<<1, 32, SEQ_SMEM>>>(X, W, bias, out);

    cudaStreamWaitEvent(0, evJ, 0);
}

// round 16
// speedup vs baseline: 2.4116x; 2.2086x over previous
#include <cuda_runtime.h>
#include <cuda_bf16.h>
#include <cstdint>
#include <cstddef>

#define NR 8192
#define DI 1024
#define DO 4096
#define C  32
#define KSEL 10
#define GAMMA_F 0.01618f
#define MARGIN 0.008f
#define FB_SLACK 0.03f
#define NEGINF (-3.4e38f)

#define B0ROWS 512                // rows prepared before seq launches
#define MIDROWS 4096              // stage-1 flag covers rows [B0ROWS, MIDROWS)

typedef unsigned long long ull;

// ---------------- static device scratch (no allocations allowed) ------------
__device__ __nv_bfloat16 g_xb[(size_t)NR * DI];   // 16 MB bf16 X
__device__ __nv_bfloat16 g_wb[(size_t)DO * DI];   //  8 MB bf16 W
__device__ float g_h[(size_t)NR * DO];            // 128 MB fp32 h (approx)
__device__ ull   g_cp[(size_t)NR * C];            // packed (h bits << 32) | idx, h-desc sorted
__device__ int   g_ci[NR * C];                    // candidate column indices
__device__ float g_cT[NR];                        // exact 33rd-largest approx h
__device__ int   g_ready;                         // staged-completion counter

// ---------------- asm helpers ----------------------------------------------
__device__ __forceinline__ uint32_t s2u(const void* p) {
    uint32_t a;
    asm("{ .reg .u64 t; cvta.to.shared.u64 t, %1; cvt.u32.u64 %0, t; }"
        : "=r"(a) : "l"(p));
    return a;
}
__device__ __forceinline__ void cpa16(uint32_t s, const void* g) {
    asm volatile("cp.async.cg.shared.global [%0], [%1], 16;" :: "r"(s), "l"(g));
}
#define CPA_COMMIT() asm volatile("cp.async.commit_group;" ::: "memory")
#define CPA_WAIT1()  asm volatile("cp.async.wait_group 1;" ::: "memory")
#define CPA_WAIT0()  asm volatile("cp.async.wait_group 0;" ::: "memory")

__device__ __forceinline__ void ldsm4(uint32_t* r, uint32_t addr) {
    asm volatile("ldmatrix.sync.aligned.m8n8.x4.shared.b16 {%0,%1,%2,%3},[%4];"
                 : "=r"(r[0]), "=r"(r[1]), "=r"(r[2]), "=r"(r[3]) : "r"(addr));
}
__device__ __forceinline__ void mma16816(float* c, const uint32_t* a, const uint32_t* b) {
    asm volatile("mma.sync.aligned.m16n8k16.row.col.f32.bf16.bf16.f32 "
                 "{%0,%1,%2,%3},{%4,%5,%6,%7},{%8,%9},{%0,%1,%2,%3};"
                 : "+f"(c[0]), "+f"(c[1]), "+f"(c[2]), "+f"(c[3])
                 : "r"(a[0]), "r"(a[1]), "r"(a[2]), "r"(a[3]), "r"(b[0]), "r"(b[1]));
}

// ---------------- tiny flag kernels ----------------------------------------
__global__ void reset_kernel()   { g_ready = 0; __threadfence(); }
__global__ void setflag_kernel() { __threadfence(); atomicAdd(&g_ready, 1); }

// ---------------- Phase 0: zero a slice of the output -----------------------
__global__ void zero_kernel(float4* __restrict__ p, int n4) {
    int i = blockIdx.x * blockDim.x + threadIdx.x;
    if (i < n4) p[i] = make_float4(0.f, 0.f, 0.f, 0.f);
}

// ---------------- Phase 0b: fp32 -> bf16 conversion ------------------------
__global__ void cvt_kernel(const float* __restrict__ X, const float* __restrict__ W) {
    const size_t NX4 = (size_t)NR * DI / 4;
    const size_t NW4 = (size_t)DO * DI / 4;
    size_t i = (size_t)blockIdx.x * blockDim.x + threadIdx.x;
    if (i >= NX4 + NW4) return;
    float4 v;
    uint2* dst;
    if (i < NX4) { v = ((const float4*)X)[i]; dst = (uint2*)g_xb + i; }
    else         { v = ((const float4*)W)[i - NX4]; dst = (uint2*)g_wb + (i - NX4); }
    uint32_t lo = (uint32_t)__bfloat16_as_ushort(__float2bfloat16_rn(v.x)) |
                  ((uint32_t)__bfloat16_as_ushort(__float2bfloat16_rn(v.y)) << 16);
    uint32_t hi = (uint32_t)__bfloat16_as_ushort(__float2bfloat16_rn(v.z)) |
                  ((uint32_t)__bfloat16_as_ushort(__float2bfloat16_rn(v.w)) << 16);
    *dst = make_uint2(lo, hi);
}

// ---------------- Phase 1: bf16 HMMA GEMM + bias + leaky -> fp32 h ---------
#define GBK 32
#define ROWB 80
#define TILEB (128 * ROWB)
#define STAGEB (2 * TILEB)
#define GSTAGES 3
#define GSMEM (GSTAGES * STAGEB)   // 61440

__global__ void __launch_bounds__(256, 1)
gemm_hmma(const float* __restrict__ bias, int rowbase) {
    extern __shared__ char sm[];
    const uint32_t sb = s2u(sm);
    const int tid = threadIdx.x;
    const int wid = tid >> 5, lane = tid & 31;
    const int row0 = rowbase + blockIdx.y * 128;
    const int col0 = blockIdx.x * 128;
    const int wm = wid & 1, wn = wid >> 1;

    auto load_stage = [&](int kt, int s) {
        const uint32_t sbase = sb + s * STAGEB;
#pragma unroll
        for (int i = 0; i < 4; ++i) {
            int item = tid + i * 256;
            int isB = item >> 9;
            int r = (item >> 2) & 127;
            int c = item & 3;
            uint32_t sa = sbase + isB * TILEB + r * ROWB + c * 16;
            const uint4* g = isB
                ? (const uint4*)g_wb + ((size_t)(col0 + r) * (DI / 8) + kt * 4 + c)
                : (const uint4*)g_xb + ((size_t)(row0 + r) * (DI / 8) + kt * 4 + c);
            cpa16(sa, g);
        }
        CPA_COMMIT();
    };

    float acc[4][4][4];
#pragma unroll
    for (int i = 0; i < 4; ++i)
#pragma unroll
        for (int j = 0; j < 4; ++j)
#pragma unroll
            for (int q = 0; q < 4; ++q) acc[i][j][q] = 0.f;

    const int NT = DI / GBK;
    load_stage(0, 0);
    load_stage(1, 1);
    CPA_WAIT1();
    __syncthreads();

#pragma unroll 1
    for (int kt = 0; kt < NT; ++kt) {
        const uint32_t Ab = sb + (kt % 3) * STAGEB;
        const uint32_t Bb = Ab + TILEB;

        uint32_t a[4][2][4], b[2][2][4];
        const int arow_l = lane & 15;
        const int asel   = (lane >> 4) & 1;
        const int g      = lane >> 3;
#pragma unroll
        for (int im = 0; im < 4; ++im)
#pragma unroll
            for (int ks = 0; ks < 2; ++ks) {
                int arow = wm * 64 + im * 16 + arow_l;
                int ach  = ks * 2 + asel;
                ldsm4(a[im][ks], Ab + arow * ROWB + ach * 16);
            }
#pragma unroll
        for (int p = 0; p < 2; ++p)
#pragma unroll
            for (int ks = 0; ks < 2; ++ks) {
                int blk = p * 2 + (g >> 1);
                int ch  = ks * 2 + (g & 1);
                int nrow = wn * 32 + blk * 8 + (lane & 7);
                ldsm4(b[p][ks], Bb + nrow * ROWB + ch * 16);
            }
#pragma unroll
        for (int im = 0; im < 4; ++im)
#pragma unroll
            for (int p = 0; p < 2; ++p)
#pragma unroll
                for (int ks = 0; ks < 2; ++ks) {
                    mma16816(acc[im][p * 2 + 0], a[im][ks], &b[p][ks][0]);
                    mma16816(acc[im][p * 2 + 1], a[im][ks], &b[p][ks][2]);
                }

        if (kt + 2 < NT) load_stage(kt + 2, (kt + 2) % 3);
        else             CPA_COMMIT();
        CPA_WAIT1();
        __syncthreads();
    }

    // epilogue: bias + leaky -> fp32 g_h, direct float2 stores
#pragma unroll
    for (int im = 0; im < 4; ++im)
#pragma unroll
        for (int in = 0; in < 4; ++in) {
            int rl = wm * 64 + im * 16 + (lane >> 2);
            int cl = wn * 32 + in * 8 + (lane & 3) * 2;
            float b0v = bias[col0 + cl], b1v = bias[col0 + cl + 1];
#pragma unroll
            for (int half = 0; half < 2; ++half) {
                float f0 = acc[im][in][half * 2 + 0] + b0v;
                float f1 = acc[im][in][half * 2 + 1] + b1v;
                f0 = f0 > 0.f ? f0 : 0.01f * f0;
                f1 = f1 > 0.f ? f1 : 0.01f * f1;
                float2* dst = (float2*)(g_h + (size_t)(row0 + rl + half * 8) * DO + col0 + cl);
                *dst = make_float2(f0, f1);
            }
        }
}

// ---------------- Phase 2: per-row top-32 candidates (exact fp32 radix) ----
__global__ void __launch_bounds__(256)
cand_kernel(int rowbase) {
    const int row = rowbase + blockIdx.x;
    const int tid = threadIdx.x;
    __shared__ unsigned skey[DO];    // 16 KB
    __shared__ unsigned hist[256];
    __shared__ unsigned s_pref;
    __shared__ int s_need, s_cnt;

    const float* h = g_h + (size_t)row * DO;
    for (int i = tid; i < DO; i += 256) {
        unsigned u = __float_as_uint(h[i]);
        u ^= (u >> 31) ? 0xFFFFFFFFu : 0x80000000u;   // monotone key
        skey[i] = u;
    }
    if (tid == 0) { s_pref = 0; s_need = C + 1; s_cnt = 0; }
    __syncthreads();

    for (int pass = 0; pass < 4; ++pass) {
        const int shift = 24 - 8 * pass;
        for (int i = tid; i < 256; i += 256) hist[i] = 0;
        __syncthreads();
        unsigned pref = s_pref;
        unsigned hm = (pass == 0) ? 0u : (0xFFFFFFFFu << (shift + 8));
        for (int i = tid; i < DO; i += 256) {
            unsigned k = skey[i];
            if (((k ^ pref) & hm) == 0) atomicAdd(&hist[(k >> shift) & 255], 1u);
        }
        __syncthreads();
        if (tid == 0) {
            int need = s_need, acc = 0, b = 255;
            for (; b >= 0; --b) { acc += (int)hist[b]; if (acc >= need) break; }
            if (b < 0) b = 0;
            s_need = need - (acc - (int)hist[b]);
            s_pref = pref | ((unsigned)b << shift);
        }
        __syncthreads();
    }
    const unsigned K33 = s_pref;

    for (int i = tid; i < DO; i += 256) {
        if (skey[i] > K33) {
            int p = atomicAdd(&s_cnt, 1);
            if (p < C) g_ci[row * C + p] = i;
        }
    }
    __syncthreads();
    for (int i = tid; i < DO; i += 256) {
        if (skey[i] == K33) {
            int p = atomicAdd(&s_cnt, 1);
            if (p < C) g_ci[row * C + p] = i;
        }
    }
    __syncthreads();
    if (tid == 0) {
        unsigned k = K33;
        g_cT[row] = __uint_as_float((k & 0x80000000u) ? (k ^ 0x80000000u) : ~k);
    }
}

// ---------------- Phase 3: exact refinement + (h desc, idx asc) sort -------
__global__ void __launch_bounds__(1024)
refine_kernel(const float* __restrict__ X, const float* __restrict__ W,
              const float* __restrict__ bias, int rowbase) {
    const int row = rowbase + blockIdx.x;
    const int tid = threadIdx.x;
    const int w = tid >> 5, lane = tid & 31;
    __shared__ float sx[DI];
    __shared__ ull s_res[C];
    sx[tid] = X[(size_t)row * DI + tid];
    __syncthreads();

    const int ci = g_ci[row * C + w];
    const float* wr = W + (size_t)ci * DI;
    float hi = 0.f, lo = 0.f;
#pragma unroll 8
    for (int i = 0; i < DI / 32; ++i) {
        int kk = i * 32 + lane;
        float a = sx[kk], b = wr[kk];
        float p  = __fmul_rn(a, b);
        float pe = __fmaf_rn(a, b, -p);
        float t  = __fadd_rn(hi, p);
        float bp = __fsub_rn(t, hi);
        float e  = __fadd_rn(__fsub_rn(hi, __fsub_rn(t, bp)), __fsub_rn(p, bp));
        hi = t;
        lo = __fadd_rn(lo, __fadd_rn(e, pe));
    }
    double d = (double)hi + (double)lo;
#pragma unroll
    for (int off = 16; off; off >>= 1) d += __shfl_xor_sync(0xFFFFFFFFu, d, off);
    if (lane == 0) {
        float hv = (float)d;                 // correctly-rounded exact dot
        hv = __fadd_rn(hv, bias[ci]);
        hv = (hv > 0.f) ? hv : __fmul_rn(0.01f, hv);
        s_res[w] = ((ull)(unsigned)__float_as_uint(hv) << 32) | (unsigned)ci;
    }
    __syncthreads();

    // warp 0: bitonic sort 32 entries by (h desc, idx asc), write sorted row
    if (tid < 32) {
        ull v = s_res[tid];
        unsigned hb = (unsigned)(v >> 32);
        unsigned mono = hb ^ ((hb >> 31) ? 0xFFFFFFFFu : 0x80000000u);
        ull sk = ((ull)mono << 32) | (ull)(0xFFFFFFFFu - (unsigned)(v & 0xFFFFFFFFu));
#pragma unroll
        for (int k2 = 2; k2 <= 32; k2 <<= 1)
#pragma unroll
            for (int j = k2 >> 1; j > 0; j >>= 1) {
                ull osk = __shfl_xor_sync(0xFFFFFFFFu, sk, j);
                ull ov  = __shfl_xor_sync(0xFFFFFFFFu, v, j);
                bool up = ((tid & k2) == 0);              // descending blocks
                bool takeBig = (((tid & j) == 0) == up);
                bool sw = takeBig ? (osk > sk) : (osk < sk);
                if (sw) { sk = osk; v = ov; }
            }
        g_cp[(size_t)row * C + tid] = v;
    }
}

// ---------------- Phase 4: sequential recurrence (one warp, smem-staged) ---
#define FB_CAP 512
#define CHR 256
#define NCH (NR / CHR)                   // 32
#define CH_BYTES (CHR * C * 8)           // 65536
#define CT_BYTES (CHR * 4)               // 1024
#define GATE1_CH (B0ROWS / CHR)          // 2  (needs flag>=1)
#define GATE2_CH (MIDROWS / CHR)         // 16 (needs flag>=2)

// dynamic smem layout (bytes)
#define SM_LR    0                       // int[4096]
#define SM_SS    16384                   // float[4096]
#define SM_SX    32768                   // float[1024]
#define SM_CAND  36864                   // int[512]
#define SM_CS    38912                   // float[512]
#define SM_CHAIN 40960                   // float[64]
#define SM_K64   41216                   // ull[32] = 256 B
#define SM_NC    41472                   // int
#define SM_CBUF  41600                   // 2 x 65536
#define SM_CT    172672                  // 2 x 1024
#define SEQ_SMEM 174720

__device__ __noinline__ void fallback_row(const float* __restrict__ X,
                                          const float* __restrict__ W,
                                          const float* __restrict__ bias,
                                          float* __restrict__ out, int t,
                                          int* s_lr, float* s_s, float* s_x,
                                          int* s_cand, float* s_cs, int* s_nc,
                                          const float* s_chain, int lane) {
    // 1) approx s from fp32 h for all columns
    const float* hrow = g_h + (size_t)t * DO;
    for (int col = lane; col < DO; col += 32) {
        int age = t - s_lr[col] - 1; if (age > 63) age = 63;
        s_s[col] = hrow[col] * s_chain[age];
    }
    if (lane == 0) *s_nc = KSEL;
    __syncwarp();

    // 2) 10 arg-max rounds over smem; winner tombstoned + seeded into s_cand
    float t10b = NEGINF;
    for (int r = 0; r < KSEL; ++r) {
        float bv = NEGINF; int bi = lane;
        for (int i = lane; i < DO; i += 32) {
            float v = s_s[i];
            if (v > bv) { bv = v; bi = i; }
        }
        float lbv = bv; int lbi = bi;
#pragma unroll
        for (int off = 16; off; off >>= 1) {
            float ov = __shfl_xor_sync(0xFFFFFFFFu, bv, off);
            int   oi = __shfl_xor_sync(0xFFFFFFFFu, bi, off);
            if (ov > bv || (ov == bv && oi < bi)) { bv = ov; bi = oi; }
        }
        t10b = bv;
        if (lbi == bi && lbv == bv) {
            s_s[bi] = NEGINF;
            s_cand[r] = bi;
        }
        __syncwarp();
    }

    // 3) sound candidate set
    const float thr = t10b - FB_SLACK;
    for (int col = lane; col < DO; col += 32) {
        if (s_s[col] >= thr) {
            int p = atomicAdd(s_nc, 1);
            if (p < FB_CAP) s_cand[p] = col;
        }
    }
    __syncwarp();
    int nc = *s_nc; if (nc > FB_CAP) nc = FB_CAP;

    // X row to shared
    for (int i = lane; i < DI; i += 32) s_x[i] = X[(size_t)t * DI + i];
    __syncwarp();

    // 4) cooperative exact fp64 refine per candidate column (coalesced)
    for (int c = 0; c < nc; ++c) {
        const int col = s_cand[c];
        const float* wr = W + (size_t)col * DI;
        double d0 = 0, d1 = 0, d2 = 0, d3 = 0;
#pragma unroll 4
        for (int q = 0; q < DI / 32; q += 4) {
            d0 = fma((double)s_x[lane + 32 * (q + 0)], (double)wr[lane + 32 * (q + 0)], d0);
            d1 = fma((double)s_x[lane + 32 * (q + 1)], (double)wr[lane + 32 * (q + 1)], d1);
            d2 = fma((double)s_x[lane + 32 * (q + 2)], (double)wr[lane + 32 * (q + 2)], d2);
            d3 = fma((double)s_x[lane + 32 * (q + 3)], (double)wr[lane + 32 * (q + 3)], d3);
        }
        double d = (d0 + d1) + (d2 + d3);
#pragma unroll
        for (int off = 16; off; off >>= 1) d += __shfl_xor_sync(0xFFFFFFFFu, d, off);
        if (lane == 0) {
            float hv = (float)d;
            hv = __fadd_rn(hv, bias[col]);
            hv = hv > 0.f ? hv : __fmul_rn(0.01f, hv);
            int age = t - s_lr[col] - 1; if (age > 63) age = 63;
            s_cs[c] = __fmul_rn(hv, s_chain[age]);
        }
    }
    __syncwarp();

    // 5) exact top-10 (value desc, column asc tiebreak)
    for (int r = 0; r < KSEL; ++r) {
        float bv = NEGINF; int bcol = 1 << 30, bslot = 0;
        for (int c = lane; c < nc; c += 32) {
            float v = s_cs[c]; int col = s_cand[c];
            if (v > bv || (v == bv && col < bcol)) { bv = v; bcol = col; bslot = c; }
        }
#pragma unroll
        for (int off = 16; off; off >>= 1) {
            float ov = __shfl_xor_sync(0xFFFFFFFFu, bv, off);
            int   oc = __shfl_xor_sync(0xFFFFFFFFu, bcol, off);
            int   os = __shfl_xor_sync(0xFFFFFFFFu, bslot, off);
            if (ov > bv || (ov == bv && oc < bcol)) { bv = ov; bcol = oc; bslot = os; }
        }
        if (!(bv > 0.f)) break;
        if (lane == 0) {
            out[(size_t)t * DO + bcol] = 1.0f;
            s_lr[bcol] = t;
            s_cs[bslot] = NEGINF;
        }
        __syncwarp();
    }
    __syncwarp();
}

__global__ void __launch_bounds__(32)
seq_kernel(const float* __restrict__ X, const float* __restrict__ W,
           const float* __restrict__ bias, float* __restrict__ out) {
    extern __shared__ char dsm[];
    const uint32_t sb = s2u(dsm);
    int*      s_lr    = (int*)(dsm + SM_LR);
    float*    s_s     = (float*)(dsm + SM_SS);
    float*    s_x     = (float*)(dsm + SM_SX);
    int*      s_cand  = (int*)(dsm + SM_CAND);
    float*    s_cs    = (float*)(dsm + SM_CS);
    float*    s_chain = (float*)(dsm + SM_CHAIN);
    ull*      s_k64   = (ull*)(dsm + SM_K64);
    int*      s_nc    = (int*)(dsm + SM_NC);
    const int lane = threadIdx.x;
    const unsigned lt = (1u << lane) - 1u;

    for (int i = lane; i < DO; i += 32) s_lr[i] = -1000000;
    if (lane == 0) {
        float c = 0.f;
        s_chain[0] = 0.f;
        for (int i = 1; i < 64; ++i) {
            c = fminf(__fadd_rn(c, GAMMA_F), 1.0f);
            s_chain[i] = c;
        }
    }
    __syncwarp();

    auto issue_chunk = [&](int ch) {
        const char* gsrc = (const char*)g_cp + (size_t)ch * CH_BYTES;
        uint32_t sdst = sb + SM_CBUF + (ch & 1) * CH_BYTES;
        for (int i = 0; i < CH_BYTES / 512; ++i)
            cpa16(sdst + lane * 16 + i * 512, gsrc + lane * 16 + i * 512);
        const char* gct = (const char*)g_cT + (size_t)ch * CT_BYTES;
        uint32_t sct = sb + SM_CT + (ch & 1) * CT_BYTES;
        cpa16(sct + lane * 16, gct + lane * 16);
        cpa16(sct + 512 + lane * 16, gct + 512 + lane * 16);
        CPA_COMMIT();
    };

    issue_chunk(0);
    issue_chunk(1);
    CPA_WAIT1();
    __syncwarp();

    for (int ch = 0; ch < NCH; ++ch) {
        const char* cbuf = dsm + SM_CBUF + (ch & 1) * CH_BYTES;
        const char* ctb  = dsm + SM_CT   + (ch & 1) * CT_BYTES;

        for (int r = 0; r < CHR; ++r) {
            const int t = ch * CHR + r;
            const ull pk  = *(const ull*)(cbuf + r * (C * 8) + lane * 8);
            const float T = *(const float*)(ctb + r * 4);
            const int   myidx = (int)(pk & 0xFFFFFFFFu);
            const float myh   = __uint_as_float((unsigned)(pk >> 32));

            int lr = s_lr[myidx];
            int age = t - lr - 1; if (age > 63) age = 63;
            const float phi = s_chain[age];
            const float s = __fmul_rn(myh, phi);
            const bool full = (phi == 1.0f);

            // ---- fast path: lanes sorted by (h desc, idx asc); top-10 are
            // the first 10 unsuppressed lanes unless a suppressed s reaches v10.
            unsigned m_full = __ballot_sync(0xFFFFFFFFu, full);
            int fr = __popc(m_full & lt);
            unsigned m9f = __ballot_sync(0xFFFFFFFFu, full && fr == 9);
            float v10 = __shfl_sync(0xFFFFFFFFu, s, m9f ? (__ffs(m9f) - 1) : 0);
            unsigned m_bad = __ballot_sync(0xFFFFFFFFu, !full && s >= v10);

            if (m9f && !m_bad && v10 > T + MARGIN) {
                if (full && fr < KSEL && s > 0.f) {
                    out[(size_t)t * DO + myidx] = 1.0f;
                    s_lr[myidx] = t;
                }
            } else {
                // ---- slow path: exact rank with (s desc, col asc) u64 keys
                float sc = s;
                if (sc == 0.0f) sc = 0.0f;        // canonicalize -0 -> +0
                unsigned u = __float_as_uint(sc);
                u ^= (u >> 31) ? 0xFFFFFFFFu : 0x80000000u;
                ull ks = ((ull)u << 32) | (ull)(0xFFFFFFFFu - (unsigned)myidx);
                s_k64[lane] = ks;
                __syncwarp();
                int cnt = 0;
#pragma unroll
                for (int j = 0; j < 16; ++j) {
                    ulonglong2 kk = *(const ulonglong2*)&s_k64[2 * j];
                    cnt += (kk.x > ks);
                    cnt += (kk.y > ks);
                }
                unsigned m9 = __ballot_sync(0xFFFFFFFFu, cnt == 9);
                float v10s = __shfl_sync(0xFFFFFFFFu, s, __ffs(m9) - 1);  // bijection
                if (v10s > T + MARGIN) {
                    if (cnt < KSEL && s > 0.f) {
                        out[(size_t)t * DO + myidx] = 1.0f;
                        s_lr[myidx] = t;
                    }
                } else {
                    fallback_row(X, W, bias, out, t, s_lr, s_s, s_x,
                                 s_cand, s_cs, s_nc, s_chain, lane);
                }
            }
            __syncwarp();
        }

        if (ch + 2 < NCH) {
            const int nxt = ch + 2;
            if (nxt == GATE1_CH) {
                if (lane == 0) while (((volatile int*)&g_ready)[0] < 1) {}
                __syncwarp();
            }
            if (nxt == GATE2_CH) {
                if (lane == 0) while (((volatile int*)&g_ready)[0] < 2) {}
                __syncwarp();
            }
            issue_chunk(nxt);
            CPA_WAIT1();
        } else {
            CPA_WAIT0();
        }
        __syncwarp();
    }
}

// ---------------- launch ----------------------------------------------------
extern "C" void kernel_launch(void* const* d_in, const int* in_sizes, int n_in,
                              void* d_out, int out_size) {
    const float* X    = (const float*)d_in[0];
    const float* W    = (const float*)d_in[1];
    const float* bias = (const float*)d_in[2];
    float* out = (float*)d_out;

    cudaFuncSetAttribute(gemm_hmma, cudaFuncAttributeMaxDynamicSharedMemorySize, GSMEM);
    cudaFuncSetAttribute(seq_kernel, cudaFuncAttributeMaxDynamicSharedMemorySize, SEQ_SMEM);

    cudaStream_t s2;
    cudaEvent_t evF, evJ;
    cudaStreamCreateWithFlags(&s2, cudaStreamNonBlocking);
    cudaEventCreateWithFlags(&evF, cudaEventDisableTiming);
    cudaEventCreateWithFlags(&evJ, cudaEventDisableTiming);

    // ---- legacy stream: minimal serial prefix for rows [0, B0ROWS) ----
    reset_kernel<<<1, 1>>>();

    const int b0n4 = B0ROWS * DO / 4;
    zero_kernel<<<(b0n4 + 255) / 256, 256>>>((float4*)out, b0n4);

    const size_t ncv = ((size_t)NR * DI + (size_t)DO * DI) / 4;
    cvt_kernel<<<(int)((ncv + 255) / 256), 256>>>(X, W);

    cudaEventRecord(evF, 0);             // fork point: after cvt

    gemm_hmma<<<dim3(DO / 128, B0ROWS / 128), 256, GSMEM>>>(bias, 0);
    cand_kernel<<<B0ROWS, 256>>>(0);
    refine_kernel<<<B0ROWS, 1024>>>(X, W, bias, 0);

    // ---- forked stream: rest of rows in two flagged stages ----
    cudaStreamWaitEvent(s2, evF, 0);
    const int restn4 = (NR - B0ROWS) * DO / 4;
    zero_kernel<<<(restn4 + 255) / 256, 256, 0, s2>>>(
        (float4*)(out + (size_t)B0ROWS * DO), restn4);

    gemm_hmma<<<dim3(DO / 128, (MIDROWS - B0ROWS) / 128), 256, GSMEM, s2>>>(bias, B0ROWS);
    cand_kernel<<<MIDROWS - B0ROWS, 256, 0, s2>>>(B0ROWS);
    refine_kernel<<<MIDROWS - B0ROWS, 1024, 0, s2>>>(X, W, bias, B0ROWS);
    setflag_kernel<<<1, 1, 0, s2>>>();

    gemm_hmma<<<dim3(DO / 128, (NR - MIDROWS) / 128), 256, GSMEM, s2>>>(bias, MIDROWS);
    cand_kernel<<<NR - MIDROWS, 256, 0, s2>>>(MIDROWS);
    refine_kernel<<<NR - MIDROWS, 1024, 0, s2>>>(X, W, bias, MIDROWS);
    setflag_kernel<<<1, 1, 0, s2>>>();
    cudaEventRecord(evJ, s2);

    // ---- seq runs concurrently with the forked branch ----
    seq_kernel<<<1, 32, SEQ_SMEM>>>(X, W, bias, out);

    cudaStreamWaitEvent(0, evJ, 0);
}